// round 2
// baseline (speedup 1.0000x reference)
#include <cuda_runtime.h>
#include <math.h>

#define Bn 8
#define Nn 8192
#define Cn 256
#define Hn 4
#define Dn 64
#define BHn (Bn*Hn)      // 32
#define SPLITS 16
#define SLICE (Nn/SPLITS) // 512

// Scratch (allocation-free rule: __device__ globals)
__device__ float g_q[BHn*Dn*Nn];              // [bh*64+dd][n]
__device__ float g_k[BHn*Dn*Nn];
__device__ float g_v[BHn*Dn*Nn];
__device__ float g_xc[Bn*Nn*Cn];              // [b,n,c]
__device__ float g_gp[BHn*SPLITS*Dn*Dn];      // split-K Gram partials
__device__ float g_attn[BHn*Dn*Dn];
__device__ float g_rq[BHn*Dn];
__device__ float g_rk[BHn*Dn];

// ---------------------------------------------------------------------------
// Generic 64x64-tile GEMM:  Y[m,c] = sum_k X[m,k] * W[c,k]  (+ bias)
// TRANSOUT writes Y in the [b*Cn + c][n] layout (per-batch channel-major).
// ---------------------------------------------------------------------------
template<bool TRANSOUT, bool BIAS>
__global__ void __launch_bounds__(256) gemm64(const float* __restrict__ X,
                                              const float* __restrict__ W,
                                              const float* __restrict__ bias,
                                              float* __restrict__ Y)
{
    __shared__ float xs[16][68];
    __shared__ float ws[16][68];
    __shared__ float outs[64][68];
    const int tx = threadIdx.x, ty = threadIdx.y;
    const int tid = ty * 16 + tx;
    const int c0 = blockIdx.x * 64;
    const int m0 = blockIdx.y * 64;
    const int lrow = tid >> 2;
    const int lk4  = (tid & 3) * 4;

    float acc[4][4] = {};

    for (int k0 = 0; k0 < Cn; k0 += 16) {
        float4 xv = *reinterpret_cast<const float4*>(X + (size_t)(m0 + lrow) * Cn + k0 + lk4);
        float4 wv = *reinterpret_cast<const float4*>(W + (size_t)(c0 + lrow) * Cn + k0 + lk4);
        __syncthreads();
        xs[lk4+0][lrow] = xv.x; xs[lk4+1][lrow] = xv.y;
        xs[lk4+2][lrow] = xv.z; xs[lk4+3][lrow] = xv.w;
        ws[lk4+0][lrow] = wv.x; ws[lk4+1][lrow] = wv.y;
        ws[lk4+2][lrow] = wv.z; ws[lk4+3][lrow] = wv.w;
        __syncthreads();
        #pragma unroll
        for (int kk = 0; kk < 16; kk++) {
            float4 a = *reinterpret_cast<const float4*>(&xs[kk][ty * 4]);
            float4 b = *reinterpret_cast<const float4*>(&ws[kk][tx * 4]);
            float av[4] = {a.x, a.y, a.z, a.w};
            float bv[4] = {b.x, b.y, b.z, b.w};
            #pragma unroll
            for (int i = 0; i < 4; i++)
                #pragma unroll
                for (int j = 0; j < 4; j++)
                    acc[i][j] += av[i] * bv[j];
        }
    }

    if (TRANSOUT) {
        __syncthreads();
        #pragma unroll
        for (int i = 0; i < 4; i++)
            #pragma unroll
            for (int j = 0; j < 4; j++)
                outs[tx * 4 + j][ty * 4 + i] = acc[i][j];   // [c_local][n_local]
        __syncthreads();
        const int b  = m0 / Nn;   // tiles never straddle a batch (Nn % 64 == 0)
        const int nb = m0 % Nn;
        #pragma unroll
        for (int r = 0; r < 4; r++) {
            int idx = r * 256 + tid;
            int cl = idx >> 4;
            int n4 = (idx & 15) * 4;
            float4 v = *reinterpret_cast<const float4*>(&outs[cl][n4]);
            *reinterpret_cast<float4*>(Y + (size_t)(b * Cn + c0 + cl) * Nn + nb + n4) = v;
        }
    } else {
        #pragma unroll
        for (int i = 0; i < 4; i++) {
            int m = m0 + ty * 4 + i;
            int c = c0 + tx * 4;
            float4 v;
            v.x = acc[i][0]; v.y = acc[i][1]; v.z = acc[i][2]; v.w = acc[i][3];
            if (BIAS) {
                v.x += bias[c + 0]; v.y += bias[c + 1];
                v.z += bias[c + 2]; v.w += bias[c + 3];
            }
            *reinterpret_cast<float4*>(Y + (size_t)m * Cn + c) = v;
        }
    }
}

// ---------------------------------------------------------------------------
// Inverse L2 norm along the token axis: out[r] = 1/max(||row r||, 1e-12)
// ---------------------------------------------------------------------------
__global__ void __launch_bounds__(256) rnorm_kernel(const float* __restrict__ Xt,
                                                    float* __restrict__ out)
{
    const int r = blockIdx.x;
    const int tid = threadIdx.x;
    const float4* p = reinterpret_cast<const float4*>(Xt + (size_t)r * Nn);
    float s = 0.f;
    #pragma unroll 4
    for (int i = tid; i < Nn / 4; i += 256) {
        float4 v = p[i];
        s += v.x * v.x + v.y * v.y + v.z * v.z + v.w * v.w;
    }
    __shared__ float red[256];
    red[tid] = s;
    __syncthreads();
    for (int st = 128; st > 0; st >>= 1) {
        if (tid < st) red[tid] += red[tid + st];
        __syncthreads();
    }
    if (tid == 0) out[r] = 1.0f / fmaxf(sqrtf(red[0]), 1e-12f);
}

// ---------------------------------------------------------------------------
// Split-K Gram partials: Gp[bh,sp][dd][e] = sum_{n in slice sp} q[dd,n]*k[e,n]
// Deterministic (no atomics): partials summed in fixed order in softmax.
// ---------------------------------------------------------------------------
__global__ void __launch_bounds__(256) gram_kernel(const float* __restrict__ Q,
                                                   const float* __restrict__ Kk,
                                                   float* __restrict__ Gp)
{
    __shared__ float qs[16][68];
    __shared__ float ks[16][68];
    const int bh = blockIdx.x;
    const int sp = blockIdx.y;
    const int tx = threadIdx.x, ty = threadIdx.y;
    const int tid = ty * 16 + tx;
    const int lrow = tid >> 2;
    const int lk4  = (tid & 3) * 4;
    const float* qb = Q + (size_t)bh * Dn * Nn;
    const float* kb = Kk + (size_t)bh * Dn * Nn;

    float acc[4][4] = {};
    const int nbeg = sp * SLICE;
    for (int n0 = nbeg; n0 < nbeg + SLICE; n0 += 16) {
        float4 qv = *reinterpret_cast<const float4*>(qb + (size_t)lrow * Nn + n0 + lk4);
        float4 kv = *reinterpret_cast<const float4*>(kb + (size_t)lrow * Nn + n0 + lk4);
        __syncthreads();
        qs[lk4+0][lrow] = qv.x; qs[lk4+1][lrow] = qv.y;
        qs[lk4+2][lrow] = qv.z; qs[lk4+3][lrow] = qv.w;
        ks[lk4+0][lrow] = kv.x; ks[lk4+1][lrow] = kv.y;
        ks[lk4+2][lrow] = kv.z; ks[lk4+3][lrow] = kv.w;
        __syncthreads();
        #pragma unroll
        for (int kk = 0; kk < 16; kk++) {
            float4 a = *reinterpret_cast<const float4*>(&qs[kk][ty * 4]);
            float4 b = *reinterpret_cast<const float4*>(&ks[kk][tx * 4]);
            float av[4] = {a.x, a.y, a.z, a.w};
            float bv[4] = {b.x, b.y, b.z, b.w};
            #pragma unroll
            for (int i = 0; i < 4; i++)
                #pragma unroll
                for (int j = 0; j < 4; j++)
                    acc[i][j] += av[i] * bv[j];
        }
    }
    float* g = Gp + ((size_t)bh * SPLITS + sp) * (Dn * Dn);
    #pragma unroll
    for (int i = 0; i < 4; i++) {
        float4 v;
        v.x = acc[i][0]; v.y = acc[i][1]; v.z = acc[i][2]; v.w = acc[i][3];
        *reinterpret_cast<float4*>(g + (ty * 4 + i) * Dn + tx * 4) = v;
    }
}

// ---------------------------------------------------------------------------
// Reduce split-K partials, apply rank-1 normalization * temperature, softmax.
// One 64-thread block per (bh, dd) row.
// ---------------------------------------------------------------------------
__global__ void __launch_bounds__(64) softmax_kernel(const float* __restrict__ Gp,
                                                     const float* __restrict__ rq,
                                                     const float* __restrict__ rk,
                                                     const float* __restrict__ temp,
                                                     float* __restrict__ A)
{
    const int r  = blockIdx.x;          // bh*64 + dd
    const int bh = r >> 6;
    const int dd = r & 63;
    const int h  = bh & 3;
    const int e  = threadIdx.x;

    float s = 0.f;
    #pragma unroll
    for (int sp = 0; sp < SPLITS; sp++)
        s += Gp[((size_t)bh * SPLITS + sp) * (Dn * Dn) + dd * Dn + e];
    s *= rq[r] * rk[bh * Dn + e] * temp[h];

    __shared__ float red[64];
    red[e] = s;
    __syncthreads();
    for (int st = 32; st > 0; st >>= 1) {
        if (e < st) red[e] = fmaxf(red[e], red[e + st]);
        __syncthreads();
    }
    float m = red[0];
    __syncthreads();
    float ex = __expf(s - m);
    red[e] = ex;
    __syncthreads();
    for (int st = 32; st > 0; st >>= 1) {
        if (e < st) red[e] += red[e + st];
        __syncthreads();
    }
    A[(size_t)bh * (Dn * Dn) + dd * Dn + e] = ex / red[0];
}

// ---------------------------------------------------------------------------
// xc[b,n, h*64+dd] = sum_e attn[bh][dd][e] * v[bh][e][n]  (written [B,N,C])
// ---------------------------------------------------------------------------
__global__ void __launch_bounds__(256) av_kernel(const float* __restrict__ A,
                                                 const float* __restrict__ V,
                                                 float* __restrict__ XC)
{
    __shared__ float as_t[64][68];   // [e][dd]
    __shared__ float vs[16][68];     // [e_local][n_local]
    __shared__ float outs[64][68];   // [n_local][c_local]
    const int bh = blockIdx.y;
    const int n0 = blockIdx.x * 64;
    const int tx = threadIdx.x, ty = threadIdx.y;
    const int tid = ty * 16 + tx;

    const float* Ab = A + (size_t)bh * (Dn * Dn);
    #pragma unroll
    for (int r = 0; r < 4; r++) {
        int idx = r * 256 + tid;
        int dd = idx >> 4;
        int e4 = (idx & 15) * 4;
        float4 v = *reinterpret_cast<const float4*>(Ab + dd * Dn + e4);
        as_t[e4+0][dd] = v.x; as_t[e4+1][dd] = v.y;
        as_t[e4+2][dd] = v.z; as_t[e4+3][dd] = v.w;
    }

    const float* vb = V + (size_t)bh * Dn * Nn;
    const int el = tid >> 4;
    const int n4 = (tid & 15) * 4;
    float acc[4][4] = {};

    #pragma unroll
    for (int e0 = 0; e0 < Dn; e0 += 16) {
        float4 vv = *reinterpret_cast<const float4*>(vb + (size_t)(e0 + el) * Nn + n0 + n4);
        __syncthreads();
        vs[el][n4+0] = vv.x; vs[el][n4+1] = vv.y;
        vs[el][n4+2] = vv.z; vs[el][n4+3] = vv.w;
        __syncthreads();
        #pragma unroll
        for (int ee = 0; ee < 16; ee++) {
            float4 a = *reinterpret_cast<const float4*>(&as_t[e0 + ee][ty * 4]);
            float4 b = *reinterpret_cast<const float4*>(&vs[ee][tx * 4]);
            float av[4] = {a.x, a.y, a.z, a.w};
            float bv[4] = {b.x, b.y, b.z, b.w};
            #pragma unroll
            for (int i = 0; i < 4; i++)
                #pragma unroll
                for (int j = 0; j < 4; j++)
                    acc[i][j] += av[i] * bv[j];
        }
    }

    __syncthreads();
    #pragma unroll
    for (int i = 0; i < 4; i++)
        #pragma unroll
        for (int j = 0; j < 4; j++)
            outs[tx * 4 + j][ty * 4 + i] = acc[i][j];
    __syncthreads();

    const int b = bh >> 2, h = bh & 3;
    #pragma unroll
    for (int r = 0; r < 4; r++) {
        int idx = r * 256 + tid;
        int nl = idx >> 4;
        int c4 = (idx & 15) * 4;
        float4 v = *reinterpret_cast<const float4*>(&outs[nl][c4]);
        *reinterpret_cast<float4*>(XC + ((size_t)(b * Nn + n0 + nl)) * Cn + h * 64 + c4) = v;
    }
}

// ---------------------------------------------------------------------------
extern "C" void kernel_launch(void* const* d_in, const int* in_sizes, int n_in,
                              void* d_out, int out_size)
{
    (void)in_sizes; (void)n_in; (void)out_size;
    const float* x1 = (const float*)d_in[0];
    const float* x2 = (const float*)d_in[1];
    const float* Wq = (const float*)d_in[2];
    const float* Wk = (const float*)d_in[3];
    const float* Wv = (const float*)d_in[4];
    const float* Wo = (const float*)d_in[5];
    const float* bo = (const float*)d_in[6];
    const float* temperature = (const float*)d_in[7];
    float* out = (float*)d_out;

    float *q, *k, *v, *xc, *gp, *attn, *rq, *rk;
    cudaGetSymbolAddress((void**)&q,    g_q);
    cudaGetSymbolAddress((void**)&k,    g_k);
    cudaGetSymbolAddress((void**)&v,    g_v);
    cudaGetSymbolAddress((void**)&xc,   g_xc);
    cudaGetSymbolAddress((void**)&gp,   g_gp);
    cudaGetSymbolAddress((void**)&attn, g_attn);
    cudaGetSymbolAddress((void**)&rq,   g_rq);
    cudaGetSymbolAddress((void**)&rk,   g_rk);

    dim3 blk(16, 16);
    dim3 gproj(Cn / 64, (Bn * Nn) / 64);

    gemm64<true, false><<<gproj, blk>>>(x1, Wq, nullptr, q);
    gemm64<true, false><<<gproj, blk>>>(x2, Wk, nullptr, k);
    gemm64<true, false><<<gproj, blk>>>(x2, Wv, nullptr, v);

    rnorm_kernel<<<BHn * Dn, 256>>>(q, rq);
    rnorm_kernel<<<BHn * Dn, 256>>>(k, rk);

    gram_kernel<<<dim3(BHn, SPLITS), blk>>>(q, k, gp);
    softmax_kernel<<<BHn * Dn, 64>>>(gp, rq, rk, temperature, attn);

    av_kernel<<<dim3(Nn / 64, BHn), blk>>>(attn, v, xc);

    gemm64<false, true><<<gproj, blk>>>(xc, Wo, bo, out);
}

// round 4
// speedup vs baseline: 2.4033x; 2.4033x over previous
#include <cuda_runtime.h>
#include <math.h>
#include <stdint.h>

#define Bn 8
#define Nn 8192
#define Cn 256
#define Hn 4
#define Dn 64
#define BHn (Bn*Hn)      // 32
#define SPLITS 16
#define SLICE (Nn/SPLITS) // 512
#define MTOT (Bn*Nn)     // 65536

// ---------------------------------------------------------------------------
// Scratch (allocation-free rule: __device__ globals)
// ---------------------------------------------------------------------------
__device__ float g_q[BHn*Dn*Nn];
__device__ float g_k[BHn*Dn*Nn];
__device__ float g_v[BHn*Dn*Nn];
__device__ float g_xc[Bn*Nn*Cn];
__device__ float g_wr[4*Cn*Cn];
__device__ float g_gp[BHn*SPLITS*Dn*Dn];
__device__ float g_attn[BHn*Dn*Dn];
__device__ float g_rq[BHn*Dn];
__device__ float g_rk[BHn*Dn];

// ---------------------------------------------------------------------------
// Helpers
// ---------------------------------------------------------------------------
__device__ __forceinline__ uint32_t smem_u32(const void* p) {
    uint32_t a;
    asm("{ .reg .u64 t; cvta.to.shared.u64 t, %1; cvt.u32.u64 %0, t; }" : "=r"(a) : "l"(p));
    return a;
}
__device__ __forceinline__ uint32_t rna_tf32_u(float x) {
    uint32_t u;
    asm("cvt.rna.tf32.f32 %0, %1;" : "=r"(u) : "f"(x));
    return u;
}
__device__ __forceinline__ float rna_tf32(float x) {
    return __uint_as_float(rna_tf32_u(x));
}
__device__ __forceinline__ void cp16(uint32_t sdst, const float* gsrc) {
    asm volatile("cp.async.cg.shared.global [%0], [%1], 16;"
                 :: "r"(sdst), "l"(__cvta_generic_to_global(gsrc)) : "memory");
}
#define CP_COMMIT() asm volatile("cp.async.commit_group;" ::: "memory")
#define CP_WAIT2()  asm volatile("cp.async.wait_group 2;" ::: "memory")

__device__ __forceinline__ void mma_tf32(float* d, const uint32_t* a, const uint32_t* b) {
    asm volatile(
        "mma.sync.aligned.m16n8k8.row.col.f32.tf32.tf32.f32 "
        "{%0,%1,%2,%3}, {%4,%5,%6,%7}, {%8,%9}, {%0,%1,%2,%3};"
        : "+f"(d[0]), "+f"(d[1]), "+f"(d[2]), "+f"(d[3])
        : "r"(a[0]), "r"(a[1]), "r"(a[2]), "r"(a[3]), "r"(b[0]), "r"(b[1]));
}

// ---------------------------------------------------------------------------
// tf32 mma.sync GEMM:  Y[m,c] = sum_k X[m,k]*W[c,k]  (M=65536, Ntot=256, K=256)
// CTA tile 128x128, warp tile 32x64 (warps 4x2), K-chunk 32, 3-stage cp.async.
// A (X) is cvt.rna'd in-loop; W must be pre-rounded to tf32.
// SMEM rows padded to 36 floats -> conflict-free fragment LDS.
// ---------------------------------------------------------------------------
#define RSTR 36
#define STG_F (128*RSTR)               // floats per stage (A or B)
#define SMEM_GEMM (3*STG_F*2*4)        // 110592 bytes

template<bool TRANSOUT, bool BIAS>
__global__ void __launch_bounds__(256, 1) gemm_mma(const float* __restrict__ X,
                                                   const float* __restrict__ W,
                                                   const float* __restrict__ bias,
                                                   float* __restrict__ Y)
{
    extern __shared__ float sm[];
    float* As = sm;                  // 3 stages [128][36]
    float* Bs = sm + 3 * STG_F;      // 3 stages [128][36]
    const uint32_t sA = smem_u32(As);
    const uint32_t sB = smem_u32(Bs);

    const int tid  = threadIdx.x;
    const int wid  = tid >> 5, lane = tid & 31;
    const int wm   = wid & 3;        // 0..3 -> M offset wm*32
    const int wn   = wid >> 2;       // 0..1 -> N offset wn*64
    const int gid  = lane >> 2;      // 0..7
    const int tig  = lane & 3;       // 0..3
    const int m0   = blockIdx.x * 128;
    const int c0   = blockIdx.y * 128;

    auto loadc = [&](int s, int k0) {
        #pragma unroll
        for (int i = 0; i < 4; i++) {
            int g = tid + i * 256;
            int r = g >> 3, kq = g & 7;
            cp16(sA + (uint32_t)(s * STG_F + r * RSTR + kq * 4) * 4,
                 X + (size_t)(m0 + r) * Cn + k0 + kq * 4);
        }
        #pragma unroll
        for (int i = 0; i < 4; i++) {
            int g = tid + i * 256;
            int r = g >> 3, kq = g & 7;
            cp16(sB + (uint32_t)(s * STG_F + r * RSTR + kq * 4) * 4,
                 W + (size_t)(c0 + r) * Cn + k0 + kq * 4);
        }
    };

    float acc[2][8][4] = {};

    #pragma unroll
    for (int c = 0; c < 3; c++) { loadc(c, c * 32); CP_COMMIT(); }

    for (int ch = 0; ch < 8; ch++) {
        CP_WAIT2();
        __syncthreads();
        const float* a = As + (ch % 3) * STG_F;
        const float* b = Bs + (ch % 3) * STG_F;

        #pragma unroll
        for (int ks = 0; ks < 4; ks++) {
            const int kk = ks * 8 + tig;
            uint32_t af[2][4];
            #pragma unroll
            for (int mt = 0; mt < 2; mt++) {
                const int row = wm * 32 + mt * 16 + gid;
                af[mt][0] = rna_tf32_u(a[row * RSTR + kk]);
                af[mt][1] = rna_tf32_u(a[(row + 8) * RSTR + kk]);
                af[mt][2] = rna_tf32_u(a[row * RSTR + kk + 4]);
                af[mt][3] = rna_tf32_u(a[(row + 8) * RSTR + kk + 4]);
            }
            uint32_t bf[8][2];
            #pragma unroll
            for (int nt = 0; nt < 8; nt++) {
                const int rowb = wn * 64 + nt * 8 + gid;
                bf[nt][0] = __float_as_uint(b[rowb * RSTR + kk]);
                bf[nt][1] = __float_as_uint(b[rowb * RSTR + kk + 4]);
            }
            #pragma unroll
            for (int mt = 0; mt < 2; mt++)
                #pragma unroll
                for (int nt = 0; nt < 8; nt++)
                    mma_tf32(acc[mt][nt], af[mt], bf[nt]);
        }

        __syncthreads();
        if (ch + 3 < 8) loadc(ch % 3, (ch + 3) * 32);
        CP_COMMIT();
    }

    // Epilogue
    #pragma unroll
    for (int mt = 0; mt < 2; mt++) {
        const int mloc = wm * 32 + mt * 16 + gid;
        #pragma unroll
        for (int nt = 0; nt < 8; nt++) {
            const int cg = c0 + wn * 64 + nt * 8 + tig * 2;
            if (TRANSOUT) {
                const int m = m0 + mloc;
                const int b = m >> 13;
                const int n = m & 8191;
                float* y0 = Y + (((size_t)(b * Cn + cg)) << 13);
                y0[n]            = acc[mt][nt][0];
                y0[8192 + n]     = acc[mt][nt][1];
                y0[n + 8]        = acc[mt][nt][2];
                y0[8192 + n + 8] = acc[mt][nt][3];
            } else {
                float b0 = 0.f, b1 = 0.f;
                if (BIAS) { b0 = __ldg(bias + cg); b1 = __ldg(bias + cg + 1); }
                float2 v0 = make_float2(acc[mt][nt][0] + b0, acc[mt][nt][1] + b1);
                float2 v1 = make_float2(acc[mt][nt][2] + b0, acc[mt][nt][3] + b1);
                *reinterpret_cast<float2*>(Y + (size_t)(m0 + mloc) * Cn + cg)     = v0;
                *reinterpret_cast<float2*>(Y + (size_t)(m0 + mloc + 8) * Cn + cg) = v1;
            }
        }
    }
}

// ---------------------------------------------------------------------------
// RNA-round to tf32 bit pattern (weights only)
// ---------------------------------------------------------------------------
__global__ void __launch_bounds__(256) round_kernel(const float4* __restrict__ in,
                                                    float4* __restrict__ out, int n4)
{
    int i = blockIdx.x * 256 + threadIdx.x;
    int stride = gridDim.x * 256;
    for (; i < n4; i += stride) {
        float4 v = in[i];
        v.x = rna_tf32(v.x); v.y = rna_tf32(v.y);
        v.z = rna_tf32(v.z); v.w = rna_tf32(v.w);
        out[i] = v;
    }
}

// ---------------------------------------------------------------------------
// Inverse L2 norm along the token axis
// ---------------------------------------------------------------------------
__global__ void __launch_bounds__(256) rnorm_kernel(const float* __restrict__ Xt,
                                                    float* __restrict__ out)
{
    const int r = blockIdx.x;
    const int tid = threadIdx.x;
    const float4* p = reinterpret_cast<const float4*>(Xt + (size_t)r * Nn);
    float s = 0.f;
    #pragma unroll 4
    for (int i = tid; i < Nn / 4; i += 256) {
        float4 v = p[i];
        s += v.x * v.x + v.y * v.y + v.z * v.z + v.w * v.w;
    }
    __shared__ float red[256];
    red[tid] = s;
    __syncthreads();
    for (int st = 128; st > 0; st >>= 1) {
        if (tid < st) red[tid] += red[tid + st];
        __syncthreads();
    }
    if (tid == 0) out[r] = 1.0f / fmaxf(sqrtf(red[0]), 1e-12f);
}

// ---------------------------------------------------------------------------
// Split-K Gram partials (fp32 SIMT, deterministic)
// ---------------------------------------------------------------------------
__global__ void __launch_bounds__(256) gram_kernel(const float* __restrict__ Q,
                                                   const float* __restrict__ Kk,
                                                   float* __restrict__ Gp)
{
    __shared__ float qs[16][68];
    __shared__ float ks[16][68];
    const int bh = blockIdx.x;
    const int sp = blockIdx.y;
    const int tx = threadIdx.x, ty = threadIdx.y;
    const int tid = ty * 16 + tx;
    const int lrow = tid >> 2;
    const int lk4  = (tid & 3) * 4;
    const float* qb = Q + (size_t)bh * Dn * Nn;
    const float* kb = Kk + (size_t)bh * Dn * Nn;

    float acc[4][4] = {};
    const int nbeg = sp * SLICE;
    for (int n0 = nbeg; n0 < nbeg + SLICE; n0 += 16) {
        float4 qv = *reinterpret_cast<const float4*>(qb + (size_t)lrow * Nn + n0 + lk4);
        float4 kv = *reinterpret_cast<const float4*>(kb + (size_t)lrow * Nn + n0 + lk4);
        __syncthreads();
        qs[lk4+0][lrow] = qv.x; qs[lk4+1][lrow] = qv.y;
        qs[lk4+2][lrow] = qv.z; qs[lk4+3][lrow] = qv.w;
        ks[lk4+0][lrow] = kv.x; ks[lk4+1][lrow] = kv.y;
        ks[lk4+2][lrow] = kv.z; ks[lk4+3][lrow] = kv.w;
        __syncthreads();
        #pragma unroll
        for (int kk = 0; kk < 16; kk++) {
            float4 a = *reinterpret_cast<const float4*>(&qs[kk][ty * 4]);
            float4 b = *reinterpret_cast<const float4*>(&ks[kk][tx * 4]);
            float av[4] = {a.x, a.y, a.z, a.w};
            float bv[4] = {b.x, b.y, b.z, b.w};
            #pragma unroll
            for (int i = 0; i < 4; i++)
                #pragma unroll
                for (int j = 0; j < 4; j++)
                    acc[i][j] += av[i] * bv[j];
        }
    }
    float* g = Gp + ((size_t)bh * SPLITS + sp) * (Dn * Dn);
    #pragma unroll
    for (int i = 0; i < 4; i++) {
        float4 v;
        v.x = acc[i][0]; v.y = acc[i][1]; v.z = acc[i][2]; v.w = acc[i][3];
        *reinterpret_cast<float4*>(g + (ty * 4 + i) * Dn + tx * 4) = v;
    }
}

// ---------------------------------------------------------------------------
// Reduce partials, rank-1 normalize * temperature, softmax
// ---------------------------------------------------------------------------
__global__ void __launch_bounds__(64) softmax_kernel(const float* __restrict__ Gp,
                                                     const float* __restrict__ rq,
                                                     const float* __restrict__ rk,
                                                     const float* __restrict__ temp,
                                                     float* __restrict__ A)
{
    const int r  = blockIdx.x;
    const int bh = r >> 6;
    const int dd = r & 63;
    const int h  = bh & 3;
    const int e  = threadIdx.x;

    float s = 0.f;
    #pragma unroll
    for (int sp = 0; sp < SPLITS; sp++)
        s += Gp[((size_t)bh * SPLITS + sp) * (Dn * Dn) + dd * Dn + e];
    s *= rq[r] * rk[bh * Dn + e] * temp[h];

    __shared__ float red[64];
    red[e] = s;
    __syncthreads();
    for (int st = 32; st > 0; st >>= 1) {
        if (e < st) red[e] = fmaxf(red[e], red[e + st]);
        __syncthreads();
    }
    float m = red[0];
    __syncthreads();
    float ex = __expf(s - m);
    red[e] = ex;
    __syncthreads();
    for (int st = 32; st > 0; st >>= 1) {
        if (e < st) red[e] += red[e + st];
        __syncthreads();
    }
    A[(size_t)bh * (Dn * Dn) + dd * Dn + e] = ex / red[0];
}

// ---------------------------------------------------------------------------
// xc[b,n,h*64+dd] = sum_e attn[bh][dd][e]*v[bh][e][n]  (written [B,N,C])
// ---------------------------------------------------------------------------
__global__ void __launch_bounds__(256) av_kernel(const float* __restrict__ A,
                                                 const float* __restrict__ V,
                                                 float* __restrict__ XC)
{
    __shared__ float as_t[64][68];
    __shared__ float vs[16][68];
    __shared__ float outs[64][68];
    const int bh = blockIdx.y;
    const int n0 = blockIdx.x * 64;
    const int tx = threadIdx.x, ty = threadIdx.y;
    const int tid = ty * 16 + tx;

    const float* Ab = A + (size_t)bh * (Dn * Dn);
    #pragma unroll
    for (int r = 0; r < 4; r++) {
        int idx = r * 256 + tid;
        int dd = idx >> 4;
        int e4 = (idx & 15) * 4;
        float4 v = *reinterpret_cast<const float4*>(Ab + dd * Dn + e4);
        as_t[e4+0][dd] = v.x; as_t[e4+1][dd] = v.y;
        as_t[e4+2][dd] = v.z; as_t[e4+3][dd] = v.w;
    }

    const float* vb = V + (size_t)bh * Dn * Nn;
    const int el = tid >> 4;
    const int n4 = (tid & 15) * 4;
    float acc[4][4] = {};

    #pragma unroll
    for (int e0 = 0; e0 < Dn; e0 += 16) {
        float4 vv = *reinterpret_cast<const float4*>(vb + (size_t)(e0 + el) * Nn + n0 + n4);
        __syncthreads();
        vs[el][n4+0] = vv.x; vs[el][n4+1] = vv.y;
        vs[el][n4+2] = vv.z; vs[el][n4+3] = vv.w;
        __syncthreads();
        #pragma unroll
        for (int ee = 0; ee < 16; ee++) {
            float4 a = *reinterpret_cast<const float4*>(&as_t[e0 + ee][ty * 4]);
            float4 b = *reinterpret_cast<const float4*>(&vs[ee][tx * 4]);
            float av[4] = {a.x, a.y, a.z, a.w};
            float bv[4] = {b.x, b.y, b.z, b.w};
            #pragma unroll
            for (int i = 0; i < 4; i++)
                #pragma unroll
                for (int j = 0; j < 4; j++)
                    acc[i][j] += av[i] * bv[j];
        }
    }

    __syncthreads();
    #pragma unroll
    for (int i = 0; i < 4; i++)
        #pragma unroll
        for (int j = 0; j < 4; j++)
            outs[tx * 4 + j][ty * 4 + i] = acc[i][j];
    __syncthreads();

    const int b = bh >> 2, h = bh & 3;
    #pragma unroll
    for (int r = 0; r < 4; r++) {
        int idx = r * 256 + tid;
        int nl = idx >> 4;
        int c4 = (idx & 15) * 4;
        float4 v = *reinterpret_cast<const float4*>(&outs[nl][c4]);
        *reinterpret_cast<float4*>(XC + ((size_t)(b * Nn + n0 + nl)) * Cn + h * 64 + c4) = v;
    }
}

// ---------------------------------------------------------------------------
extern "C" void kernel_launch(void* const* d_in, const int* in_sizes, int n_in,
                              void* d_out, int out_size)
{
    (void)in_sizes; (void)n_in; (void)out_size;
    const float* x1 = (const float*)d_in[0];
    const float* x2 = (const float*)d_in[1];
    const float* Wq = (const float*)d_in[2];
    const float* Wk = (const float*)d_in[3];
    const float* Wv = (const float*)d_in[4];
    const float* Wo = (const float*)d_in[5];
    const float* bo = (const float*)d_in[6];
    const float* temperature = (const float*)d_in[7];
    float* out = (float*)d_out;

    float *q, *k, *v, *xc, *wr, *gp, *attn, *rq, *rk;
    cudaGetSymbolAddress((void**)&q,    g_q);
    cudaGetSymbolAddress((void**)&k,    g_k);
    cudaGetSymbolAddress((void**)&v,    g_v);
    cudaGetSymbolAddress((void**)&xc,   g_xc);
    cudaGetSymbolAddress((void**)&wr,   g_wr);
    cudaGetSymbolAddress((void**)&gp,   g_gp);
    cudaGetSymbolAddress((void**)&attn, g_attn);
    cudaGetSymbolAddress((void**)&rq,   g_rq);
    cudaGetSymbolAddress((void**)&rk,   g_rk);

    cudaFuncSetAttribute(gemm_mma<true,  false>, cudaFuncAttributeMaxDynamicSharedMemorySize, SMEM_GEMM);
    cudaFuncSetAttribute(gemm_mma<false, true >, cudaFuncAttributeMaxDynamicSharedMemorySize, SMEM_GEMM);

    const int nW4 = (Cn * Cn) / 4;
    round_kernel<<<64, 256>>>((const float4*)Wq, (float4*)(wr + 0 * Cn * Cn), nW4);
    round_kernel<<<64, 256>>>((const float4*)Wk, (float4*)(wr + 1 * Cn * Cn), nW4);
    round_kernel<<<64, 256>>>((const float4*)Wv, (float4*)(wr + 2 * Cn * Cn), nW4);
    round_kernel<<<64, 256>>>((const float4*)Wo, (float4*)(wr + 3 * Cn * Cn), nW4);

    dim3 ggrid(MTOT / 128, Cn / 128);
    gemm_mma<true,  false><<<ggrid, 256, SMEM_GEMM>>>(x1, wr + 0 * Cn * Cn, nullptr, q);
    gemm_mma<true,  false><<<ggrid, 256, SMEM_GEMM>>>(x2, wr + 1 * Cn * Cn, nullptr, k);
    gemm_mma<true,  false><<<ggrid, 256, SMEM_GEMM>>>(x2, wr + 2 * Cn * Cn, nullptr, v);

    rnorm_kernel<<<BHn * Dn, 256>>>(q, rq);
    rnorm_kernel<<<BHn * Dn, 256>>>(k, rk);

    dim3 blk(16, 16);
    gram_kernel<<<dim3(BHn, SPLITS), blk>>>(q, k, gp);
    softmax_kernel<<<BHn * Dn, 64>>>(gp, rq, rk, temperature, attn);
    av_kernel<<<dim3(Nn / 64, BHn), blk>>>(attn, v, xc);

    gemm_mma<false, true><<<ggrid, 256, SMEM_GEMM>>>(xc, wr + 3 * Cn * Cn, bo, out);
}

// round 5
// speedup vs baseline: 3.2835x; 1.3663x over previous
#include <cuda_runtime.h>
#include <cuda_fp16.h>
#include <math.h>
#include <stdint.h>

#define Bn 8
#define Nn 8192
#define Cn 256
#define Hn 4
#define Dn 64
#define BHn (Bn*Hn)
#define SPLITS 16
#define SLICE (Nn/SPLITS)
#define MTOT (Bn*Nn)

// ---------------------------------------------------------------------------
// Scratch (__device__ globals; no allocation allowed)
// ---------------------------------------------------------------------------
__device__ float  g_q [Bn*Cn*Nn];          // [b*256 + c][n]
__device__ float  g_kv[Bn*512*Nn];         // [b*512 + c][n]; c<256 = k, c>=256 = v
__device__ __half g_x1h[Bn*Nn*Cn];
__device__ __half g_x2h[Bn*Nn*Cn];
__device__ __half g_wh[4*Cn*Cn];           // Wq, Wk, Wv, Wo (rounded to fp16)
__device__ __half g_xch[Bn*Nn*Cn];
__device__ float  g_gp[BHn*SPLITS*Dn*Dn];
__device__ float  g_attn[BHn*Dn*Dn];
__device__ float  g_rq[BHn*Dn];
__device__ float  g_rk[BHn*Dn];

// ---------------------------------------------------------------------------
// Helpers
// ---------------------------------------------------------------------------
__device__ __forceinline__ uint32_t smem_u32(const void* p) {
    uint32_t a;
    asm("{ .reg .u64 t; cvta.to.shared.u64 t, %1; cvt.u32.u64 %0, t; }" : "=r"(a) : "l"(p));
    return a;
}
__device__ __forceinline__ void cp16(uint32_t sdst, const void* gsrc) {
    asm volatile("cp.async.cg.shared.global [%0], [%1], 16;"
                 :: "r"(sdst), "l"(__cvta_generic_to_global(gsrc)) : "memory");
}
#define CP_COMMIT() asm volatile("cp.async.commit_group;" ::: "memory")
#define CP_WAIT2()  asm volatile("cp.async.wait_group 2;" ::: "memory")

#define LDSM4(r0, r1, r2, r3, addr) \
    asm volatile("ldmatrix.sync.aligned.m8n8.x4.shared.b16 {%0,%1,%2,%3}, [%4];" \
                 : "=r"(r0), "=r"(r1), "=r"(r2), "=r"(r3) : "r"(addr))

__device__ __forceinline__ void mma_f16(float* d, const uint32_t* a, const uint32_t* b) {
    asm volatile(
        "mma.sync.aligned.m16n8k16.row.col.f32.f16.f16.f32 "
        "{%0,%1,%2,%3}, {%4,%5,%6,%7}, {%8,%9}, {%0,%1,%2,%3};"
        : "+f"(d[0]), "+f"(d[1]), "+f"(d[2]), "+f"(d[3])
        : "r"(a[0]), "r"(a[1]), "r"(a[2]), "r"(a[3]), "r"(b[0]), "r"(b[1]));
}

// ---------------------------------------------------------------------------
// fp16 mma GEMM:  Y[m,c] = sum_k Xh[m,k]*Wh[c,k]   (fp32 accum)
// CTA tile 128x128, warp tile 32x64, K chunk 32, 4-stage cp.async, ldmatrix.
// TRANSOUT: Y[( (m>>13)*CT + c )*8192 + (m&8191)] (per-batch channel-major).
// ---------------------------------------------------------------------------
#define RSH 40                       // halves per smem row (80B, LDSM conflict-free)
#define STG_B (128*RSH*2)            // 10240 bytes per stage per operand
#define SMEM_GEMM (2*4*STG_B)        // 81920

template<bool TRANSOUT, bool BIAS>
__global__ void __launch_bounds__(256, 2) gemm_h(const __half* __restrict__ X,
                                                 const __half* __restrict__ W,
                                                 const float* __restrict__ bias,
                                                 float* __restrict__ Y, int CT)
{
    extern __shared__ char sm[];
    const uint32_t sA = smem_u32(sm);
    const uint32_t sB = sA + 4 * STG_B;

    const int tid  = threadIdx.x;
    const int wid  = tid >> 5, lane = tid & 31;
    const int wm   = wid & 3;
    const int wn   = wid >> 2;
    const int gid  = lane >> 2;
    const int tig  = lane & 3;
    const int m0   = blockIdx.x * 128;
    const int c0   = blockIdx.y * 128;

    // ldmatrix lane offsets (in halves): tile t = lane>>3, row-in-tile = lane&7
    const int lrA = ((lane >> 3) & 1) * 8 + (lane & 7);   // m within 16-tile
    const int lkA = (lane >> 4) * 8;                       // k offset 0/8
    const int lrB = (lane >> 4) * 8 + (lane & 7);          // n within 16-tile
    const int lkB = ((lane >> 3) & 1) * 8;
    int aoff[2], boff[4];
    #pragma unroll
    for (int mt = 0; mt < 2; mt++)
        aoff[mt] = (wm * 32 + mt * 16 + lrA) * RSH + lkA;
    #pragma unroll
    for (int nb = 0; nb < 4; nb++)
        boff[nb] = (wn * 64 + nb * 16 + lrB) * RSH + lkB;

    auto loadc = [&](int st, int k0) {
        #pragma unroll
        for (int i = 0; i < 2; i++) {
            int g = tid + i * 256;                 // 512 16B chunks for A
            int r = g >> 2, kq = g & 3;
            cp16(sA + st * STG_B + (r * RSH + kq * 8) * 2,
                 X + (size_t)(m0 + r) * Cn + k0 + kq * 8);
        }
        #pragma unroll
        for (int i = 0; i < 2; i++) {
            int g = tid + i * 256;
            int r = g >> 2, kq = g & 3;
            cp16(sB + st * STG_B + (r * RSH + kq * 8) * 2,
                 W + (size_t)(c0 + r) * Cn + k0 + kq * 8);
        }
    };

    float acc[2][8][4] = {};

    #pragma unroll
    for (int c = 0; c < 3; c++) { loadc(c, c * 32); CP_COMMIT(); }

    for (int ch = 0; ch < 8; ch++) {
        CP_WAIT2();
        __syncthreads();
        const int st = ch & 3;
        const uint32_t a0 = sA + st * STG_B;
        const uint32_t b0a = sB + st * STG_B;

        #pragma unroll
        for (int ks = 0; ks < 2; ks++) {
            uint32_t af[2][4];
            #pragma unroll
            for (int mt = 0; mt < 2; mt++)
                LDSM4(af[mt][0], af[mt][1], af[mt][2], af[mt][3],
                      a0 + (aoff[mt] + ks * 16) * 2);
            uint32_t bf[8][2];
            #pragma unroll
            for (int nb = 0; nb < 4; nb++) {
                uint32_t r0, r1, r2, r3;
                LDSM4(r0, r1, r2, r3, b0a + (boff[nb] + ks * 16) * 2);
                bf[nb * 2][0] = r0; bf[nb * 2][1] = r1;
                bf[nb * 2 + 1][0] = r2; bf[nb * 2 + 1][1] = r3;
            }
            #pragma unroll
            for (int mt = 0; mt < 2; mt++)
                #pragma unroll
                for (int nt = 0; nt < 8; nt++)
                    mma_f16(acc[mt][nt], af[mt], bf[nt]);
        }

        if (ch + 3 < 8) loadc((ch + 3) & 3, (ch + 3) * 32);
        CP_COMMIT();
    }

    // Epilogue
    #pragma unroll
    for (int mt = 0; mt < 2; mt++) {
        const int mloc = wm * 32 + mt * 16 + gid;
        #pragma unroll
        for (int nt = 0; nt < 8; nt++) {
            const int cg = c0 + wn * 64 + nt * 8 + tig * 2;
            if (TRANSOUT) {
                const int m = m0 + mloc;
                const int b = m >> 13;
                const int n = m & 8191;
                float* y0 = Y + (((size_t)(b * CT + cg)) << 13);
                y0[n]            = acc[mt][nt][0];
                y0[8192 + n]     = acc[mt][nt][1];
                y0[n + 8]        = acc[mt][nt][2];
                y0[8192 + n + 8] = acc[mt][nt][3];
            } else {
                float b0 = 0.f, b1 = 0.f;
                if (BIAS) { b0 = __ldg(bias + cg); b1 = __ldg(bias + cg + 1); }
                float2 v0 = make_float2(acc[mt][nt][0] + b0, acc[mt][nt][1] + b1);
                float2 v1 = make_float2(acc[mt][nt][2] + b0, acc[mt][nt][3] + b1);
                *reinterpret_cast<float2*>(Y + (size_t)(m0 + mloc) * Cn + cg)     = v0;
                *reinterpret_cast<float2*>(Y + (size_t)(m0 + mloc + 8) * Cn + cg) = v1;
            }
        }
    }
}

// ---------------------------------------------------------------------------
// f32 -> f16 converters
// ---------------------------------------------------------------------------
__device__ __forceinline__ void cvt_store4(__half* dst, float4 v) {
    __half2 h0 = __floats2half2_rn(v.x, v.y);
    __half2 h1 = __floats2half2_rn(v.z, v.w);
    uint2 u;
    u.x = *reinterpret_cast<uint32_t*>(&h0);
    u.y = *reinterpret_cast<uint32_t*>(&h1);
    *reinterpret_cast<uint2*>(dst) = u;
}

__global__ void __launch_bounds__(256) cvt_x_kernel(const float4* __restrict__ x1,
                                                    const float4* __restrict__ x2,
                                                    __half* h1, __half* h2)
{
    const int n4 = (Bn * Nn * Cn) / 4;
    const float4* src = blockIdx.y ? x2 : x1;
    __half* dst = blockIdx.y ? h2 : h1;
    int i = blockIdx.x * 256 + threadIdx.x;
    int stride = gridDim.x * 256;
    for (; i < n4; i += stride) cvt_store4(dst + i * 4, src[i]);
}

__global__ void __launch_bounds__(256) cvt_w_kernel(const float4* __restrict__ wq,
                                                    const float4* __restrict__ wk,
                                                    const float4* __restrict__ wv,
                                                    const float4* __restrict__ wo,
                                                    __half* dst)
{
    const int n4 = (Cn * Cn) / 4;
    const float4* src = blockIdx.y == 0 ? wq : blockIdx.y == 1 ? wk :
                        blockIdx.y == 2 ? wv : wo;
    __half* d = dst + (size_t)blockIdx.y * Cn * Cn;
    int i = blockIdx.x * 256 + threadIdx.x;
    if (i < n4) cvt_store4(d + i * 4, src[i]);
}

// ---------------------------------------------------------------------------
// Inverse L2 norm along token axis; row = (r>>8)*RS + (r&255)
// ---------------------------------------------------------------------------
__global__ void __launch_bounds__(256) rnorm_kernel(const float* __restrict__ Xt,
                                                    float* __restrict__ out, int RS)
{
    const int r = blockIdx.x;
    const int row = (r >> 8) * RS + (r & 255);
    const int tid = threadIdx.x;
    const float4* p = reinterpret_cast<const float4*>(Xt + (size_t)row * Nn);
    float s = 0.f;
    #pragma unroll 4
    for (int i = tid; i < Nn / 4; i += 256) {
        float4 v = p[i];
        s += v.x * v.x + v.y * v.y + v.z * v.z + v.w * v.w;
    }
    __shared__ float red[256];
    red[tid] = s;
    __syncthreads();
    for (int st = 128; st > 0; st >>= 1) {
        if (tid < st) red[tid] += red[tid + st];
        __syncthreads();
    }
    if (tid == 0) out[r] = 1.0f / fmaxf(sqrtf(red[0]), 1e-12f);
}

// ---------------------------------------------------------------------------
// Split-K Gram partials (fp32 SIMT, deterministic)
// ---------------------------------------------------------------------------
__global__ void __launch_bounds__(256) gram_kernel(const float* __restrict__ Q,
                                                   const float* __restrict__ KV,
                                                   float* __restrict__ Gp)
{
    __shared__ float qs[16][68];
    __shared__ float ks[16][68];
    const int bh = blockIdx.x;
    const int sp = blockIdx.y;
    const int tx = threadIdx.x, ty = threadIdx.y;
    const int tid = ty * 16 + tx;
    const int lrow = tid >> 2;
    const int lk4  = (tid & 3) * 4;
    const float* qb = Q + (size_t)bh * Dn * Nn;
    const float* kb = KV + ((size_t)(bh >> 2) * 512 + (bh & 3) * 64) * Nn;

    float acc[4][4] = {};
    const int nbeg = sp * SLICE;
    for (int n0 = nbeg; n0 < nbeg + SLICE; n0 += 16) {
        float4 qv = *reinterpret_cast<const float4*>(qb + (size_t)lrow * Nn + n0 + lk4);
        float4 kv = *reinterpret_cast<const float4*>(kb + (size_t)lrow * Nn + n0 + lk4);
        __syncthreads();
        qs[lk4+0][lrow] = qv.x; qs[lk4+1][lrow] = qv.y;
        qs[lk4+2][lrow] = qv.z; qs[lk4+3][lrow] = qv.w;
        ks[lk4+0][lrow] = kv.x; ks[lk4+1][lrow] = kv.y;
        ks[lk4+2][lrow] = kv.z; ks[lk4+3][lrow] = kv.w;
        __syncthreads();
        #pragma unroll
        for (int kk = 0; kk < 16; kk++) {
            float4 a = *reinterpret_cast<const float4*>(&qs[kk][ty * 4]);
            float4 b = *reinterpret_cast<const float4*>(&ks[kk][tx * 4]);
            float av[4] = {a.x, a.y, a.z, a.w};
            float bv[4] = {b.x, b.y, b.z, b.w};
            #pragma unroll
            for (int i = 0; i < 4; i++)
                #pragma unroll
                for (int j = 0; j < 4; j++)
                    acc[i][j] += av[i] * bv[j];
        }
    }
    float* g = Gp + ((size_t)bh * SPLITS + sp) * (Dn * Dn);
    #pragma unroll
    for (int i = 0; i < 4; i++) {
        float4 v;
        v.x = acc[i][0]; v.y = acc[i][1]; v.z = acc[i][2]; v.w = acc[i][3];
        *reinterpret_cast<float4*>(g + (ty * 4 + i) * Dn + tx * 4) = v;
    }
}

// ---------------------------------------------------------------------------
// Reduce partials, rank-1 normalize * temperature, softmax
// ---------------------------------------------------------------------------
__global__ void __launch_bounds__(64) softmax_kernel(const float* __restrict__ Gp,
                                                     const float* __restrict__ rq,
                                                     const float* __restrict__ rk,
                                                     const float* __restrict__ temp,
                                                     float* __restrict__ A)
{
    const int r  = blockIdx.x;
    const int bh = r >> 6;
    const int dd = r & 63;
    const int h  = bh & 3;
    const int e  = threadIdx.x;

    float s = 0.f;
    #pragma unroll
    for (int sp = 0; sp < SPLITS; sp++)
        s += Gp[((size_t)bh * SPLITS + sp) * (Dn * Dn) + dd * Dn + e];
    s *= rq[r] * rk[bh * Dn + e] * temp[h];

    __shared__ float red[64];
    red[e] = s;
    __syncthreads();
    for (int st = 32; st > 0; st >>= 1) {
        if (e < st) red[e] = fmaxf(red[e], red[e + st]);
        __syncthreads();
    }
    float m = red[0];
    __syncthreads();
    float ex = __expf(s - m);
    red[e] = ex;
    __syncthreads();
    for (int st = 32; st > 0; st >>= 1) {
        if (e < st) red[e] += red[e + st];
        __syncthreads();
    }
    A[(size_t)bh * (Dn * Dn) + dd * Dn + e] = ex / red[0];
}

// ---------------------------------------------------------------------------
// xc[b,n,h*64+dd] = sum_e attn[bh][dd][e]*v[bh][e][n]; output written fp16
// ---------------------------------------------------------------------------
__global__ void __launch_bounds__(256) av_kernel(const float* __restrict__ A,
                                                 const float* __restrict__ KV,
                                                 __half* __restrict__ XC)
{
    __shared__ float as_t[64][68];
    __shared__ float vs[16][68];
    __shared__ float outs[64][68];
    const int bh = blockIdx.y;
    const int n0 = blockIdx.x * 64;
    const int tx = threadIdx.x, ty = threadIdx.y;
    const int tid = ty * 16 + tx;

    const float* Ab = A + (size_t)bh * (Dn * Dn);
    #pragma unroll
    for (int r = 0; r < 4; r++) {
        int idx = r * 256 + tid;
        int dd = idx >> 4;
        int e4 = (idx & 15) * 4;
        float4 v = *reinterpret_cast<const float4*>(Ab + dd * Dn + e4);
        as_t[e4+0][dd] = v.x; as_t[e4+1][dd] = v.y;
        as_t[e4+2][dd] = v.z; as_t[e4+3][dd] = v.w;
    }

    const float* vb = KV + ((size_t)(bh >> 2) * 512 + 256 + (bh & 3) * 64) * Nn;
    const int el = tid >> 4;
    const int n4 = (tid & 15) * 4;
    float acc[4][4] = {};

    #pragma unroll
    for (int e0 = 0; e0 < Dn; e0 += 16) {
        float4 vv = *reinterpret_cast<const float4*>(vb + (size_t)(e0 + el) * Nn + n0 + n4);
        __syncthreads();
        vs[el][n4+0] = vv.x; vs[el][n4+1] = vv.y;
        vs[el][n4+2] = vv.z; vs[el][n4+3] = vv.w;
        __syncthreads();
        #pragma unroll
        for (int ee = 0; ee < 16; ee++) {
            float4 a = *reinterpret_cast<const float4*>(&as_t[e0 + ee][ty * 4]);
            float4 b = *reinterpret_cast<const float4*>(&vs[ee][tx * 4]);
            float av[4] = {a.x, a.y, a.z, a.w};
            float bv[4] = {b.x, b.y, b.z, b.w};
            #pragma unroll
            for (int i = 0; i < 4; i++)
                #pragma unroll
                for (int j = 0; j < 4; j++)
                    acc[i][j] += av[i] * bv[j];
        }
    }

    __syncthreads();
    #pragma unroll
    for (int i = 0; i < 4; i++)
        #pragma unroll
        for (int j = 0; j < 4; j++)
            outs[tx * 4 + j][ty * 4 + i] = acc[i][j];
    __syncthreads();

    const int b = bh >> 2, h = bh & 3;
    #pragma unroll
    for (int r = 0; r < 4; r++) {
        int idx = r * 256 + tid;
        int nl = idx >> 4;
        int c4 = (idx & 15) * 4;
        float4 v = *reinterpret_cast<const float4*>(&outs[nl][c4]);
        cvt_store4(XC + ((size_t)(b * Nn + n0 + nl)) * Cn + h * 64 + c4, v);
    }
}

// ---------------------------------------------------------------------------
extern "C" void kernel_launch(void* const* d_in, const int* in_sizes, int n_in,
                              void* d_out, int out_size)
{
    (void)in_sizes; (void)n_in; (void)out_size;
    const float* x1 = (const float*)d_in[0];
    const float* x2 = (const float*)d_in[1];
    const float* Wq = (const float*)d_in[2];
    const float* Wk = (const float*)d_in[3];
    const float* Wv = (const float*)d_in[4];
    const float* Wo = (const float*)d_in[5];
    const float* bo = (const float*)d_in[6];
    const float* temperature = (const float*)d_in[7];
    float* out = (float*)d_out;

    float *q, *kv, *gp, *attn, *rq, *rk;
    __half *x1h, *x2h, *wh, *xch;
    cudaGetSymbolAddress((void**)&q,    g_q);
    cudaGetSymbolAddress((void**)&kv,   g_kv);
    cudaGetSymbolAddress((void**)&x1h,  g_x1h);
    cudaGetSymbolAddress((void**)&x2h,  g_x2h);
    cudaGetSymbolAddress((void**)&wh,   g_wh);
    cudaGetSymbolAddress((void**)&xch,  g_xch);
    cudaGetSymbolAddress((void**)&gp,   g_gp);
    cudaGetSymbolAddress((void**)&attn, g_attn);
    cudaGetSymbolAddress((void**)&rq,   g_rq);
    cudaGetSymbolAddress((void**)&rk,   g_rk);

    cudaFuncSetAttribute(gemm_h<true,  false>, cudaFuncAttributeMaxDynamicSharedMemorySize, SMEM_GEMM);
    cudaFuncSetAttribute(gemm_h<false, true >, cudaFuncAttributeMaxDynamicSharedMemorySize, SMEM_GEMM);

    cvt_w_kernel<<<dim3(64, 4), 256>>>((const float4*)Wq, (const float4*)Wk,
                                       (const float4*)Wv, (const float4*)Wo, wh);
    cvt_x_kernel<<<dim3(1024, 2), 256>>>((const float4*)x1, (const float4*)x2, x1h, x2h);

    gemm_h<true, false><<<dim3(MTOT / 128, 2), 256, SMEM_GEMM>>>(x1h, wh, nullptr, q, 256);
    gemm_h<true, false><<<dim3(MTOT / 128, 4), 256, SMEM_GEMM>>>(x2h, wh + Cn * Cn, nullptr, kv, 512);

    rnorm_kernel<<<Bn * Cn, 256>>>(q, rq, 256);
    rnorm_kernel<<<Bn * Cn, 256>>>(kv, rk, 512);

    dim3 blk(16, 16);
    gram_kernel<<<dim3(BHn, SPLITS), blk>>>(q, kv, gp);
    softmax_kernel<<<BHn * Dn, 64>>>(gp, rq, rk, temperature, attn);
    av_kernel<<<dim3(Nn / 64, BHn), blk>>>(attn, kv, xch);

    gemm_h<false, true><<<dim3(MTOT / 128, 2), 256, SMEM_GEMM>>>(xch, wh + 3 * Cn * Cn, bo, out, 256);
}

// round 6
// speedup vs baseline: 4.9716x; 1.5141x over previous
#include <cuda_runtime.h>
#include <cuda_fp16.h>
#include <math.h>
#include <stdint.h>

#define Bn 8
#define Nn 8192
#define Cn 256
#define Hn 4
#define Dn 64
#define BHn (Bn*Hn)
#define MTOT (Bn*Nn)
#define GSP 8            // gram split-K
#define GSL (Nn/GSP)     // 1024 tokens per gram slice
#define NSL 16           // sumsq slices

// ---------------------------------------------------------------------------
// Scratch (__device__ globals; no allocation allowed)
// ---------------------------------------------------------------------------
__device__ __half g_x1h[MTOT*Cn];
__device__ __half g_x2h[MTOT*Cn];
__device__ __half g_qh [MTOT*Cn];         // [b*8192+n][256] row-major
__device__ __half g_kvh[(size_t)MTOT*512];// [b*8192+n][512]; c<256 = k, c>=256 = v
__device__ __half g_wh [3*Cn*Cn];         // Wq, Wk, Wv fp16
__device__ __half g_wfh[Bn*Cn*Cn];        // folded Wo per batch, fp16
__device__ float  g_gp [BHn*GSP*Dn*Dn];   // gram split-K partials
__device__ float  g_attn[BHn*Dn*Dn];
__device__ float  g_nss[2*Bn*NSL*Cn];     // sumsq partials: [q/k][b][slice][c]

// ---------------------------------------------------------------------------
// Helpers
// ---------------------------------------------------------------------------
__device__ __forceinline__ uint32_t smem_u32(const void* p) {
    uint32_t a;
    asm("{ .reg .u64 t; cvta.to.shared.u64 t, %1; cvt.u32.u64 %0, t; }" : "=r"(a) : "l"(p));
    return a;
}
__device__ __forceinline__ void cp16(uint32_t sdst, const void* gsrc) {
    asm volatile("cp.async.cg.shared.global [%0], [%1], 16;"
                 :: "r"(sdst), "l"(__cvta_generic_to_global(gsrc)) : "memory");
}
#define CP_COMMIT() asm volatile("cp.async.commit_group;" ::: "memory")
#define CP_WAIT2()  asm volatile("cp.async.wait_group 2;" ::: "memory")
#define CP_WAIT1()  asm volatile("cp.async.wait_group 1;" ::: "memory")

#define LDSM4(r0, r1, r2, r3, addr) \
    asm volatile("ldmatrix.sync.aligned.m8n8.x4.shared.b16 {%0,%1,%2,%3}, [%4];" \
                 : "=r"(r0), "=r"(r1), "=r"(r2), "=r"(r3) : "r"(addr))
#define LDSM4T(r0, r1, r2, r3, addr) \
    asm volatile("ldmatrix.sync.aligned.m8n8.x4.trans.shared.b16 {%0,%1,%2,%3}, [%4];" \
                 : "=r"(r0), "=r"(r1), "=r"(r2), "=r"(r3) : "r"(addr))
#define LDSM2T(r0, r1, addr) \
    asm volatile("ldmatrix.sync.aligned.m8n8.x2.trans.shared.b16 {%0,%1}, [%2];" \
                 : "=r"(r0), "=r"(r1) : "r"(addr))

__device__ __forceinline__ void mma_f16(float* d, const uint32_t* a, const uint32_t* b) {
    asm volatile(
        "mma.sync.aligned.m16n8k16.row.col.f32.f16.f16.f32 "
        "{%0,%1,%2,%3}, {%4,%5,%6,%7}, {%8,%9}, {%0,%1,%2,%3};"
        : "+f"(d[0]), "+f"(d[1]), "+f"(d[2]), "+f"(d[3])
        : "r"(a[0]), "r"(a[1]), "r"(a[2]), "r"(a[3]), "r"(b[0]), "r"(b[1]));
}

// ---------------------------------------------------------------------------
// fp16 mma GEMM:  Y[m,c] = sum_k X[m*lda + aoff + k] * W[c,k]   (K=256)
// CTA tile 128x128, warp tile 32x64, K chunk 32, 4-stage cp.async, ldmatrix.
// OUTF32=false: fp16 row-major output (stride ct), no bias.
// OUTF32=true : fp32 row-major + bias, per-batch W (W + (m0>>13)*65536).
// ---------------------------------------------------------------------------
#define RSH 40
#define STG_B (128*RSH*2)
#define SMEM_GEMM (2*4*STG_B)   // 81920

template<bool OUTF32>
__global__ void __launch_bounds__(256, 2) gemm_h(const __half* __restrict__ X,
                                                 const __half* __restrict__ W,
                                                 const float* __restrict__ bias,
                                                 float* __restrict__ Y,
                                                 __half* __restrict__ Yh,
                                                 int lda, int aoff, int ct)
{
    extern __shared__ char sm[];
    const uint32_t sA = smem_u32(sm);
    const uint32_t sB = sA + 4 * STG_B;

    const int tid  = threadIdx.x;
    const int wid  = tid >> 5, lane = tid & 31;
    const int wm   = wid & 3;
    const int wn   = wid >> 2;
    const int gid  = lane >> 2;
    const int tig  = lane & 3;
    const int m0   = blockIdx.x * 128;
    const int c0   = blockIdx.y * 128;

    const __half* Wp = OUTF32 ? W + ((size_t)(m0 >> 13) << 16) : W;

    const int lrA = ((lane >> 3) & 1) * 8 + (lane & 7);
    const int lkA = (lane >> 4) * 8;
    const int lrB = (lane >> 4) * 8 + (lane & 7);
    const int lkB = ((lane >> 3) & 1) * 8;
    int aoffs[2], boffs[4];
    #pragma unroll
    for (int mt = 0; mt < 2; mt++) aoffs[mt] = (wm * 32 + mt * 16 + lrA) * RSH + lkA;
    #pragma unroll
    for (int nb = 0; nb < 4; nb++) boffs[nb] = (wn * 64 + nb * 16 + lrB) * RSH + lkB;

    auto loadc = [&](int st, int k0) {
        #pragma unroll
        for (int i = 0; i < 2; i++) {
            int g = tid + i * 256;
            int r = g >> 2, kq = g & 3;
            cp16(sA + st * STG_B + (r * RSH + kq * 8) * 2,
                 X + (size_t)(m0 + r) * lda + aoff + k0 + kq * 8);
        }
        #pragma unroll
        for (int i = 0; i < 2; i++) {
            int g = tid + i * 256;
            int r = g >> 2, kq = g & 3;
            cp16(sB + st * STG_B + (r * RSH + kq * 8) * 2,
                 Wp + (size_t)(c0 + r) * Cn + k0 + kq * 8);
        }
    };

    float acc[2][8][4] = {};

    #pragma unroll
    for (int c = 0; c < 3; c++) { loadc(c, c * 32); CP_COMMIT(); }

    for (int ch = 0; ch < 8; ch++) {
        CP_WAIT2();
        __syncthreads();
        if (ch + 3 < 8) loadc((ch + 3) & 3, (ch + 3) * 32);
        CP_COMMIT();

        const int st = ch & 3;
        const uint32_t a0 = sA + st * STG_B;
        const uint32_t b0a = sB + st * STG_B;

        #pragma unroll
        for (int ks = 0; ks < 2; ks++) {
            uint32_t af[2][4];
            #pragma unroll
            for (int mt = 0; mt < 2; mt++)
                LDSM4(af[mt][0], af[mt][1], af[mt][2], af[mt][3],
                      a0 + (aoffs[mt] + ks * 16) * 2);
            uint32_t bf[8][2];
            #pragma unroll
            for (int nb = 0; nb < 4; nb++) {
                uint32_t r0, r1, r2, r3;
                LDSM4(r0, r1, r2, r3, b0a + (boffs[nb] + ks * 16) * 2);
                bf[nb * 2][0] = r0; bf[nb * 2][1] = r1;
                bf[nb * 2 + 1][0] = r2; bf[nb * 2 + 1][1] = r3;
            }
            #pragma unroll
            for (int mt = 0; mt < 2; mt++)
                #pragma unroll
                for (int nt = 0; nt < 8; nt++)
                    mma_f16(acc[mt][nt], af[mt], bf[nt]);
        }
    }

    #pragma unroll
    for (int mt = 0; mt < 2; mt++) {
        const int mloc = wm * 32 + mt * 16 + gid;
        const int m = m0 + mloc;
        #pragma unroll
        for (int nt = 0; nt < 8; nt++) {
            const int cg = c0 + wn * 64 + nt * 8 + tig * 2;
            if (OUTF32) {
                float b0 = __ldg(bias + cg), b1 = __ldg(bias + cg + 1);
                float2 v0 = make_float2(acc[mt][nt][0] + b0, acc[mt][nt][1] + b1);
                float2 v1 = make_float2(acc[mt][nt][2] + b0, acc[mt][nt][3] + b1);
                *reinterpret_cast<float2*>(Y + (size_t)m * ct + cg)       = v0;
                *reinterpret_cast<float2*>(Y + (size_t)(m + 8) * ct + cg) = v1;
            } else {
                __half2 h0 = __floats2half2_rn(acc[mt][nt][0], acc[mt][nt][1]);
                __half2 h1 = __floats2half2_rn(acc[mt][nt][2], acc[mt][nt][3]);
                *reinterpret_cast<__half2*>(Yh + (size_t)m * ct + cg)       = h0;
                *reinterpret_cast<__half2*>(Yh + (size_t)(m + 8) * ct + cg) = h1;
            }
        }
    }
}

// ---------------------------------------------------------------------------
// Gram via fp16 mma with ldmatrix.trans:
// Gp[bh,sp][dd][e] = sum_{n in slice} qh[b,n,h*64+dd] * kh[b,n,h*64+e]
// Block: (bh, sp). 8 warps, each owns n8 = w*8 output columns. Chunks of 64 n.
// ---------------------------------------------------------------------------
#define GRS 72                    // halves per smem row (token row), pad
#define GSTG (64*GRS*2)           // 9216 bytes per operand stage

__global__ void __launch_bounds__(256, 2) gram_mma(const __half* __restrict__ Qh,
                                                   const __half* __restrict__ KVh,
                                                   float* __restrict__ Gp)
{
    __shared__ char smg[4 * GSTG];
    const uint32_t sq = smem_u32(smg);
    const uint32_t sk = sq + 2 * GSTG;

    const int bh = blockIdx.x, sp = blockIdx.y;
    const int b = bh >> 2, h = bh & 3;
    const int tid = threadIdx.x;
    const int w = tid >> 5, lane = tid & 31;
    const int gid = lane >> 2, tig = lane & 3;
    const int t0 = sp * GSL;

    const __half* qb = Qh + ((size_t)b * Nn) * 256 + h * 64;
    const __half* kb = KVh + ((size_t)b * Nn) * 512 + h * 64;

    auto gload = [&](int st, int tc) {
        #pragma unroll
        for (int i = 0; i < 2; i++) {
            int g = tid + i * 256;
            int r = g >> 3, ck = g & 7;
            cp16(sq + st * GSTG + (r * GRS + ck * 8) * 2,
                 qb + (size_t)(t0 + tc + r) * 256 + ck * 8);
        }
        #pragma unroll
        for (int i = 0; i < 2; i++) {
            int g = tid + i * 256;
            int r = g >> 3, ck = g & 7;
            cp16(sk + st * GSTG + (r * GRS + ck * 8) * 2,
                 kb + (size_t)(t0 + tc + r) * 512 + ck * 8);
        }
    };

    // ldmatrix.trans lane address components (in halves)
    const int aH = (((lane >> 4) & 1) * 8 + (lane & 7)) * GRS + ((lane >> 3) & 1) * 8;
    const int bH = (((lane >> 3) & 1) * 8 + (lane & 7)) * GRS + w * 8;

    float acc[4][4] = {};

    gload(0, 0);  CP_COMMIT();
    gload(1, 64); CP_COMMIT();

    for (int c = 0; c < 16; c++) {
        CP_WAIT1();
        __syncthreads();
        const uint32_t aq = sq + (c & 1) * GSTG;
        const uint32_t ak = sk + (c & 1) * GSTG;

        #pragma unroll
        for (int st16 = 0; st16 < 4; st16++) {
            const int kb16 = st16 * 16;
            uint32_t bfr[2];
            LDSM2T(bfr[0], bfr[1], ak + (kb16 * GRS + bH) * 2);
            #pragma unroll
            for (int mt = 0; mt < 4; mt++) {
                uint32_t af[4];
                LDSM4T(af[0], af[1], af[2], af[3],
                       aq + (kb16 * GRS + aH + mt * 16) * 2);
                mma_f16(acc[mt], af, bfr);
            }
        }
        __syncthreads();
        if (c + 2 < 16) gload(c & 1, (c + 2) * 64);
        CP_COMMIT();
    }

    float* g = Gp + (((size_t)bh * GSP + sp) << 12);
    #pragma unroll
    for (int mt = 0; mt < 4; mt++) {
        const int r0 = mt * 16 + gid;
        *reinterpret_cast<float2*>(g + r0 * 64 + w * 8 + tig * 2) =
            make_float2(acc[mt][0], acc[mt][1]);
        *reinterpret_cast<float2*>(g + (r0 + 8) * 64 + w * 8 + tig * 2) =
            make_float2(acc[mt][2], acc[mt][3]);
    }
}

// ---------------------------------------------------------------------------
// f32 -> f16 converters
// ---------------------------------------------------------------------------
__device__ __forceinline__ void cvt_store4(__half* dst, float4 v) {
    __half2 h0 = __floats2half2_rn(v.x, v.y);
    __half2 h1 = __floats2half2_rn(v.z, v.w);
    uint2 u;
    u.x = *reinterpret_cast<uint32_t*>(&h0);
    u.y = *reinterpret_cast<uint32_t*>(&h1);
    *reinterpret_cast<uint2*>(dst) = u;
}

__global__ void __launch_bounds__(256) cvt_x_kernel(const float4* __restrict__ x1,
                                                    const float4* __restrict__ x2,
                                                    __half* h1, __half* h2)
{
    const int n4 = (MTOT * Cn) / 4;
    const float4* src = blockIdx.y ? x2 : x1;
    __half* dst = blockIdx.y ? h2 : h1;
    int i = blockIdx.x * 256 + threadIdx.x;
    int stride = gridDim.x * 256;
    for (; i < n4; i += stride) cvt_store4(dst + i * 4, src[i]);
}

__global__ void __launch_bounds__(256) cvt_w_kernel(const float4* __restrict__ wq,
                                                    const float4* __restrict__ wk,
                                                    const float4* __restrict__ wv,
                                                    __half* dst)
{
    const int n4 = (Cn * Cn) / 4;
    const float4* src = blockIdx.y == 0 ? wq : blockIdx.y == 1 ? wk : wv;
    __half* d = dst + (size_t)blockIdx.y * Cn * Cn;
    int i = blockIdx.x * 256 + threadIdx.x;
    if (i < n4) cvt_store4(d + i * 4, src[i]);
}

// ---------------------------------------------------------------------------
// Column sum-of-squares partials over token slices (coalesced)
// nss[z][b][sl][c] = sum_{n in slice} x[b,n,c]^2,  z=0: qh(ld 256), z=1: kvh k-half(ld 512)
// ---------------------------------------------------------------------------
__global__ void __launch_bounds__(256) sumsq_kernel(const __half* __restrict__ Qh,
                                                    const __half* __restrict__ KVh,
                                                    float* __restrict__ nss)
{
    const int sl = blockIdx.x, b = blockIdx.y, z = blockIdx.z;
    const int c = threadIdx.x;
    const __half* base;
    size_t ld;
    if (z == 0) { base = Qh + ((size_t)b * Nn + sl * (Nn / NSL)) * 256 + c; ld = 256; }
    else        { base = KVh + ((size_t)b * Nn + sl * (Nn / NSL)) * 512 + c; ld = 512; }
    float s = 0.f;
    #pragma unroll 8
    for (int n = 0; n < Nn / NSL; n++) {
        float v = __half2float(base[(size_t)n * ld]);
        s += v * v;
    }
    nss[(((size_t)z * Bn + b) * NSL + sl) * Cn + c] = s;
}

// ---------------------------------------------------------------------------
// Reduce gram partials + norms, rank-1 normalize * temperature, softmax
// ---------------------------------------------------------------------------
__global__ void __launch_bounds__(64) softmax_kernel(const float* __restrict__ Gp,
                                                     const float* __restrict__ nss,
                                                     const float* __restrict__ temp,
                                                     float* __restrict__ A)
{
    const int r  = blockIdx.x;
    const int bh = r >> 6;
    const int dd = r & 63;
    const int b  = bh >> 2, h = bh & 3;
    const int e  = threadIdx.x;

    float qsum = 0.f, ksum = 0.f;
    #pragma unroll
    for (int sl = 0; sl < NSL; sl++) {
        qsum += nss[(((size_t)0 * Bn + b) * NSL + sl) * Cn + h * 64 + dd];
        ksum += nss[(((size_t)1 * Bn + b) * NSL + sl) * Cn + h * 64 + e];
    }
    const float rq = 1.0f / fmaxf(sqrtf(qsum), 1e-12f);
    const float rk = 1.0f / fmaxf(sqrtf(ksum), 1e-12f);

    float s = 0.f;
    #pragma unroll
    for (int sp = 0; sp < GSP; sp++)
        s += Gp[(((size_t)bh * GSP + sp) << 12) + dd * 64 + e];
    s *= rq * rk * temp[h];

    __shared__ float red[64];
    red[e] = s;
    __syncthreads();
    for (int st = 32; st > 0; st >>= 1) {
        if (e < st) red[e] = fmaxf(red[e], red[e + st]);
        __syncthreads();
    }
    float m = red[0];
    __syncthreads();
    float ex = __expf(s - m);
    red[e] = ex;
    __syncthreads();
    for (int st = 32; st > 0; st >>= 1) {
        if (e < st) red[e] += red[e + st];
        __syncthreads();
    }
    A[(size_t)bh * 4096 + dd * 64 + e] = ex / red[0];
}

// ---------------------------------------------------------------------------
// Fold attn into Wo: Wf[b][c][h*64+e] = sum_dd Wo[c][h*64+dd] * attn[bh][dd][e]
// ---------------------------------------------------------------------------
__global__ void __launch_bounds__(256) fold_kernel(const float* __restrict__ A,
                                                   const float* __restrict__ Wo,
                                                   __half* __restrict__ Wf)
{
    __shared__ float at[64][65];
    __shared__ float wo[64][65];
    const int bh = blockIdx.x, cq = blockIdx.y;
    const int b = bh >> 2, h = bh & 3;
    const int t = threadIdx.x;

    const float* Ab = A + (size_t)bh * 4096;
    #pragma unroll
    for (int i = 0; i < 16; i++) {
        int idx = t + i * 256;
        at[idx >> 6][idx & 63] = Ab[idx];
    }
    const float* Wob = Wo + (size_t)(cq * 64) * 256 + h * 64;
    #pragma unroll
    for (int i = 0; i < 16; i++) {
        int idx = t + i * 256;
        wo[idx >> 6][idx & 63] = Wob[(size_t)(idx >> 6) * 256 + (idx & 63)];
    }
    __syncthreads();

    const int e = t & 63, clb = t >> 6;
    #pragma unroll
    for (int i = 0; i < 16; i++) {
        const int cl = clb * 16 + i;
        float s = 0.f;
        #pragma unroll
        for (int dd = 0; dd < 64; dd++) s += wo[cl][dd] * at[dd][e];
        Wf[(((size_t)b * 256 + cq * 64 + cl) << 8) + h * 64 + e] = __float2half(s);
    }
}

// ---------------------------------------------------------------------------
extern "C" void kernel_launch(void* const* d_in, const int* in_sizes, int n_in,
                              void* d_out, int out_size)
{
    (void)in_sizes; (void)n_in; (void)out_size;
    const float* x1 = (const float*)d_in[0];
    const float* x2 = (const float*)d_in[1];
    const float* Wq = (const float*)d_in[2];
    const float* Wk = (const float*)d_in[3];
    const float* Wv = (const float*)d_in[4];
    const float* Wo = (const float*)d_in[5];
    const float* bo = (const float*)d_in[6];
    const float* temperature = (const float*)d_in[7];
    float* out = (float*)d_out;

    __half *x1h, *x2h, *qh, *kvh, *wh, *wfh;
    float *gp, *attn, *nss;
    cudaGetSymbolAddress((void**)&x1h, g_x1h);
    cudaGetSymbolAddress((void**)&x2h, g_x2h);
    cudaGetSymbolAddress((void**)&qh,  g_qh);
    cudaGetSymbolAddress((void**)&kvh, g_kvh);
    cudaGetSymbolAddress((void**)&wh,  g_wh);
    cudaGetSymbolAddress((void**)&wfh, g_wfh);
    cudaGetSymbolAddress((void**)&gp,  g_gp);
    cudaGetSymbolAddress((void**)&attn, g_attn);
    cudaGetSymbolAddress((void**)&nss, g_nss);

    cudaFuncSetAttribute(gemm_h<false>, cudaFuncAttributeMaxDynamicSharedMemorySize, SMEM_GEMM);
    cudaFuncSetAttribute(gemm_h<true >, cudaFuncAttributeMaxDynamicSharedMemorySize, SMEM_GEMM);

    cvt_w_kernel<<<dim3(64, 3), 256>>>((const float4*)Wq, (const float4*)Wk,
                                       (const float4*)Wv, wh);
    cvt_x_kernel<<<dim3(1024, 2), 256>>>((const float4*)x1, (const float4*)x2, x1h, x2h);

    // q = x1 @ Wq^T  -> qh row-major [m][256]
    gemm_h<false><<<dim3(MTOT / 128, 2), 256, SMEM_GEMM>>>(
        x1h, wh, nullptr, nullptr, qh, 256, 0, 256);
    // [k|v] = x2 @ [Wk;Wv]^T -> kvh row-major [m][512]
    gemm_h<false><<<dim3(MTOT / 128, 4), 256, SMEM_GEMM>>>(
        x2h, wh + Cn * Cn, nullptr, nullptr, kvh, 256, 0, 512);

    sumsq_kernel<<<dim3(NSL, Bn, 2), 256>>>(qh, kvh, nss);
    gram_mma<<<dim3(BHn, GSP), 256>>>(qh, kvh, gp);
    softmax_kernel<<<BHn * Dn, 64>>>(gp, nss, temperature, attn);
    fold_kernel<<<dim3(BHn, 4), 256>>>(attn, Wo, wfh);

    // out = v^T-layout A (kvh cols 256..511) @ Wfold_b^T + bo
    gemm_h<true><<<dim3(MTOT / 128, 2), 256, SMEM_GEMM>>>(
        kvh, wfh, bo, out, nullptr, 512, 256, 256);
}

// round 7
// speedup vs baseline: 5.2473x; 1.0555x over previous
#include <cuda_runtime.h>
#include <cuda_fp16.h>
#include <math.h>
#include <stdint.h>

#define Bn 8
#define Nn 8192
#define Cn 256
#define Hn 4
#define Dn 64
#define BHn (Bn*Hn)
#define MTOT (Bn*Nn)
#define GSP 8            // gram split-K
#define GSL (Nn/GSP)
#define NSL 16           // sumsq slices

// ---------------------------------------------------------------------------
// Scratch (__device__ globals; no allocation allowed)
// ---------------------------------------------------------------------------
__device__ __half g_x1h[MTOT*Cn];
__device__ __half g_x2h[MTOT*Cn];
__device__ __half g_qh [MTOT*Cn];          // [b*8192+n][256]
__device__ __half g_kh [MTOT*Cn];          // [b*8192+n][256]
__device__ __half g_wh [2*Cn*Cn];          // Wq, Wk fp16
__device__ __half g_w2h[Bn*Cn*Cn];         // folded weight per batch fp16
__device__ float  g_u  [Bn*Cn*Cn];         // fold1 intermediate fp32
__device__ float  g_gp [BHn*GSP*Dn*Dn];
__device__ float  g_attn[BHn*Dn*Dn];
__device__ float  g_nss[2*Bn*NSL*Cn];

// ---------------------------------------------------------------------------
// Helpers
// ---------------------------------------------------------------------------
__device__ __forceinline__ uint32_t smem_u32(const void* p) {
    uint32_t a;
    asm("{ .reg .u64 t; cvta.to.shared.u64 t, %1; cvt.u32.u64 %0, t; }" : "=r"(a) : "l"(p));
    return a;
}
__device__ __forceinline__ void cp16(uint32_t sdst, const void* gsrc) {
    asm volatile("cp.async.cg.shared.global [%0], [%1], 16;"
                 :: "r"(sdst), "l"(__cvta_generic_to_global(gsrc)) : "memory");
}
#define CP_COMMIT() asm volatile("cp.async.commit_group;" ::: "memory")
#define CP_WAIT2()  asm volatile("cp.async.wait_group 2;" ::: "memory")
#define CP_WAIT1()  asm volatile("cp.async.wait_group 1;" ::: "memory")

#define LDSM4(r0, r1, r2, r3, addr) \
    asm volatile("ldmatrix.sync.aligned.m8n8.x4.shared.b16 {%0,%1,%2,%3}, [%4];" \
                 : "=r"(r0), "=r"(r1), "=r"(r2), "=r"(r3) : "r"(addr))
#define LDSM4T(r0, r1, r2, r3, addr) \
    asm volatile("ldmatrix.sync.aligned.m8n8.x4.trans.shared.b16 {%0,%1,%2,%3}, [%4];" \
                 : "=r"(r0), "=r"(r1), "=r"(r2), "=r"(r3) : "r"(addr))
#define LDSM2T(r0, r1, addr) \
    asm volatile("ldmatrix.sync.aligned.m8n8.x2.trans.shared.b16 {%0,%1}, [%2];" \
                 : "=r"(r0), "=r"(r1) : "r"(addr))

__device__ __forceinline__ void mma_f16(float* d, const uint32_t* a, const uint32_t* b) {
    asm volatile(
        "mma.sync.aligned.m16n8k16.row.col.f32.f16.f16.f32 "
        "{%0,%1,%2,%3}, {%4,%5,%6,%7}, {%8,%9}, {%0,%1,%2,%3};"
        : "+f"(d[0]), "+f"(d[1]), "+f"(d[2]), "+f"(d[3])
        : "r"(a[0]), "r"(a[1]), "r"(a[2]), "r"(a[3]), "r"(b[0]), "r"(b[1]));
}

// ---------------------------------------------------------------------------
// fp16 mma GEMM, CTA tile 128x256 (full N), 512 threads (warps 4Mx4N, 32x64),
// K=256 in 8 chunks of 32, 4-stage cp.async + ldmatrix.
// OUTF32=false: blockIdx.z selects (X0,W0 -> Yh0) or (X1,W1 -> Yh1), fp16 out.
// OUTF32=true : A=X0, W=W0 + per-batch offset ((m0>>13)<<16), fp32 out + bias.
// ---------------------------------------------------------------------------
#define RSH 40
#define A_STG (128*RSH*2)               // 10240 B
#define B_STG (256*RSH*2)               // 20480 B
#define SMEM_G (4*(A_STG+B_STG))        // 122880 B

template<bool OUTF32>
__global__ void __launch_bounds__(512, 1) gemm_h(const __half* __restrict__ X0,
                                                 const __half* __restrict__ W0,
                                                 __half* __restrict__ Yh0,
                                                 const __half* __restrict__ X1,
                                                 const __half* __restrict__ W1,
                                                 __half* __restrict__ Yh1,
                                                 const float* __restrict__ bias,
                                                 float* __restrict__ Yf)
{
    extern __shared__ char sm[];
    const uint32_t sA = smem_u32(sm);
    const uint32_t sB = sA + 4 * A_STG;

    const int tid  = threadIdx.x;
    const int wid  = tid >> 5, lane = tid & 31;
    const int wm   = wid & 3;
    const int wn   = wid >> 2;          // 0..3
    const int gid  = lane >> 2;
    const int tig  = lane & 3;
    const int m0   = blockIdx.x * 128;

    const __half* X;
    const __half* Wp;
    __half* Yh;
    if (OUTF32) {
        X = X0; Wp = W0 + ((size_t)(m0 >> 13) << 16); Yh = nullptr;
    } else {
        const int z = blockIdx.z;
        X  = z ? X1 : X0;
        Wp = z ? W1 : W0;
        Yh = z ? Yh1 : Yh0;
    }

    const int lrA = ((lane >> 3) & 1) * 8 + (lane & 7);
    const int lkA = (lane >> 4) * 8;
    const int lrB = (lane >> 4) * 8 + (lane & 7);
    const int lkB = ((lane >> 3) & 1) * 8;
    int aoffs[2], boffs[4];
    #pragma unroll
    for (int mt = 0; mt < 2; mt++) aoffs[mt] = (wm * 32 + mt * 16 + lrA) * RSH + lkA;
    #pragma unroll
    for (int nb = 0; nb < 4; nb++) boffs[nb] = (wn * 64 + nb * 16 + lrB) * RSH + lkB;

    auto loadc = [&](int st, int k0) {
        {   // A: 128 rows x 32 halves = 512 cp16
            int r = tid >> 2, kq = tid & 3;
            cp16(sA + st * A_STG + (r * RSH + kq * 8) * 2,
                 X + (size_t)(m0 + r) * Cn + k0 + kq * 8);
        }
        #pragma unroll
        for (int i = 0; i < 2; i++) {   // B: 256 rows x 32 halves = 1024 cp16
            int g = tid + i * 512;
            int r = g >> 2, kq = g & 3;
            cp16(sB + st * B_STG + (r * RSH + kq * 8) * 2,
                 Wp + (size_t)r * Cn + k0 + kq * 8);
        }
    };

    float acc[2][8][4] = {};

    #pragma unroll
    for (int c = 0; c < 3; c++) { loadc(c, c * 32); CP_COMMIT(); }

    for (int ch = 0; ch < 8; ch++) {
        CP_WAIT2();
        __syncthreads();
        if (ch + 3 < 8) loadc((ch + 3) & 3, (ch + 3) * 32);
        CP_COMMIT();

        const int st = ch & 3;
        const uint32_t a0 = sA + st * A_STG;
        const uint32_t b0a = sB + st * B_STG;

        #pragma unroll
        for (int ks = 0; ks < 2; ks++) {
            uint32_t af[2][4];
            #pragma unroll
            for (int mt = 0; mt < 2; mt++)
                LDSM4(af[mt][0], af[mt][1], af[mt][2], af[mt][3],
                      a0 + (aoffs[mt] + ks * 16) * 2);
            uint32_t bf[8][2];
            #pragma unroll
            for (int nb = 0; nb < 4; nb++) {
                uint32_t r0, r1, r2, r3;
                LDSM4(r0, r1, r2, r3, b0a + (boffs[nb] + ks * 16) * 2);
                bf[nb * 2][0] = r0; bf[nb * 2][1] = r1;
                bf[nb * 2 + 1][0] = r2; bf[nb * 2 + 1][1] = r3;
            }
            #pragma unroll
            for (int mt = 0; mt < 2; mt++)
                #pragma unroll
                for (int nt = 0; nt < 8; nt++)
                    mma_f16(acc[mt][nt], af[mt], bf[nt]);
        }
    }

    #pragma unroll
    for (int mt = 0; mt < 2; mt++) {
        const int m = m0 + wm * 32 + mt * 16 + gid;
        #pragma unroll
        for (int nt = 0; nt < 8; nt++) {
            const int cg = wn * 64 + nt * 8 + tig * 2;
            if (OUTF32) {
                float b0 = __ldg(bias + cg), b1 = __ldg(bias + cg + 1);
                float2 v0 = make_float2(acc[mt][nt][0] + b0, acc[mt][nt][1] + b1);
                float2 v1 = make_float2(acc[mt][nt][2] + b0, acc[mt][nt][3] + b1);
                *reinterpret_cast<float2*>(Yf + (size_t)m * Cn + cg)       = v0;
                *reinterpret_cast<float2*>(Yf + (size_t)(m + 8) * Cn + cg) = v1;
            } else {
                __half2 h0 = __floats2half2_rn(acc[mt][nt][0], acc[mt][nt][1]);
                __half2 h1 = __floats2half2_rn(acc[mt][nt][2], acc[mt][nt][3]);
                *reinterpret_cast<__half2*>(Yh + (size_t)m * Cn + cg)       = h0;
                *reinterpret_cast<__half2*>(Yh + (size_t)(m + 8) * Cn + cg) = h1;
            }
        }
    }
}

// ---------------------------------------------------------------------------
// Gram via fp16 mma with ldmatrix.trans (both operands 256-stride now)
// ---------------------------------------------------------------------------
#define GRS 72
#define GSTG (64*GRS*2)

__global__ void __launch_bounds__(256, 2) gram_mma(const __half* __restrict__ Qh,
                                                   const __half* __restrict__ Kh,
                                                   float* __restrict__ Gp)
{
    __shared__ char smg[4 * GSTG];
    const uint32_t sq = smem_u32(smg);
    const uint32_t sk = sq + 2 * GSTG;

    const int bh = blockIdx.x, sp = blockIdx.y;
    const int b = bh >> 2, h = bh & 3;
    const int tid = threadIdx.x;
    const int w = tid >> 5, lane = tid & 31;
    const int gid = lane >> 2, tig = lane & 3;
    const int t0 = sp * GSL;

    const __half* qb = Qh + ((size_t)b * Nn) * 256 + h * 64;
    const __half* kb = Kh + ((size_t)b * Nn) * 256 + h * 64;

    auto gload = [&](int st, int tc) {
        #pragma unroll
        for (int i = 0; i < 2; i++) {
            int g = tid + i * 256;
            int r = g >> 3, ck = g & 7;
            cp16(sq + st * GSTG + (r * GRS + ck * 8) * 2,
                 qb + (size_t)(t0 + tc + r) * 256 + ck * 8);
        }
        #pragma unroll
        for (int i = 0; i < 2; i++) {
            int g = tid + i * 256;
            int r = g >> 3, ck = g & 7;
            cp16(sk + st * GSTG + (r * GRS + ck * 8) * 2,
                 kb + (size_t)(t0 + tc + r) * 256 + ck * 8);
        }
    };

    const int aH = (((lane >> 4) & 1) * 8 + (lane & 7)) * GRS + ((lane >> 3) & 1) * 8;
    const int bH = (((lane >> 3) & 1) * 8 + (lane & 7)) * GRS + w * 8;

    float acc[4][4] = {};

    gload(0, 0);  CP_COMMIT();
    gload(1, 64); CP_COMMIT();

    for (int c = 0; c < 16; c++) {
        CP_WAIT1();
        __syncthreads();
        const uint32_t aq = sq + (c & 1) * GSTG;
        const uint32_t ak = sk + (c & 1) * GSTG;

        #pragma unroll
        for (int st16 = 0; st16 < 4; st16++) {
            const int kb16 = st16 * 16;
            uint32_t bfr[2];
            LDSM2T(bfr[0], bfr[1], ak + (kb16 * GRS + bH) * 2);
            #pragma unroll
            for (int mt = 0; mt < 4; mt++) {
                uint32_t af[4];
                LDSM4T(af[0], af[1], af[2], af[3],
                       aq + (kb16 * GRS + aH + mt * 16) * 2);
                mma_f16(acc[mt], af, bfr);
            }
        }
        __syncthreads();
        if (c + 2 < 16) gload(c & 1, (c + 2) * 64);
        CP_COMMIT();
    }

    float* g = Gp + (((size_t)bh * GSP + sp) << 12);
    #pragma unroll
    for (int mt = 0; mt < 4; mt++) {
        const int r0 = mt * 16 + gid;
        *reinterpret_cast<float2*>(g + r0 * 64 + w * 8 + tig * 2) =
            make_float2(acc[mt][0], acc[mt][1]);
        *reinterpret_cast<float2*>(g + (r0 + 8) * 64 + w * 8 + tig * 2) =
            make_float2(acc[mt][2], acc[mt][3]);
    }
}

// ---------------------------------------------------------------------------
// f32 -> f16 converters
// ---------------------------------------------------------------------------
__device__ __forceinline__ void cvt_store4(__half* dst, float4 v) {
    __half2 h0 = __floats2half2_rn(v.x, v.y);
    __half2 h1 = __floats2half2_rn(v.z, v.w);
    uint2 u;
    u.x = *reinterpret_cast<uint32_t*>(&h0);
    u.y = *reinterpret_cast<uint32_t*>(&h1);
    *reinterpret_cast<uint2*>(dst) = u;
}

__global__ void __launch_bounds__(256) cvt_x_kernel(const float4* __restrict__ x1,
                                                    const float4* __restrict__ x2,
                                                    __half* h1, __half* h2)
{
    const int n4 = (MTOT * Cn) / 4;
    const float4* src = blockIdx.y ? x2 : x1;
    __half* dst = blockIdx.y ? h2 : h1;
    int i = blockIdx.x * 256 + threadIdx.x;
    int stride = gridDim.x * 256;
    for (; i < n4; i += stride) cvt_store4(dst + i * 4, src[i]);
}

__global__ void __launch_bounds__(256) cvt_w_kernel(const float4* __restrict__ wq,
                                                    const float4* __restrict__ wk,
                                                    __half* dst)
{
    const int n4 = (Cn * Cn) / 4;
    const float4* src = blockIdx.y == 0 ? wq : wk;
    __half* d = dst + (size_t)blockIdx.y * Cn * Cn;
    int i = blockIdx.x * 256 + threadIdx.x;
    if (i < n4) cvt_store4(d + i * 4, src[i]);
}

// ---------------------------------------------------------------------------
// Column sum-of-squares partials (both q and k are 256-stride)
// ---------------------------------------------------------------------------
__global__ void __launch_bounds__(256) sumsq_kernel(const __half* __restrict__ Qh,
                                                    const __half* __restrict__ Kh,
                                                    float* __restrict__ nss)
{
    const int sl = blockIdx.x, b = blockIdx.y, z = blockIdx.z;
    const int c = threadIdx.x;
    const __half* base = (z == 0 ? Qh : Kh) + ((size_t)b * Nn + sl * (Nn / NSL)) * 256 + c;
    float s = 0.f;
    #pragma unroll 8
    for (int n = 0; n < Nn / NSL; n++) {
        float v = __half2float(base[(size_t)n * 256]);
        s += v * v;
    }
    nss[(((size_t)z * Bn + b) * NSL + sl) * Cn + c] = s;
}

// ---------------------------------------------------------------------------
// Reduce gram partials + norms, rank-1 normalize * temperature, softmax
// ---------------------------------------------------------------------------
__global__ void __launch_bounds__(64) softmax_kernel(const float* __restrict__ Gp,
                                                     const float* __restrict__ nss,
                                                     const float* __restrict__ temp,
                                                     float* __restrict__ A)
{
    const int r  = blockIdx.x;
    const int bh = r >> 6;
    const int dd = r & 63;
    const int b  = bh >> 2, h = bh & 3;
    const int e  = threadIdx.x;

    float qsum = 0.f, ksum = 0.f;
    #pragma unroll
    for (int sl = 0; sl < NSL; sl++) {
        qsum += nss[(((size_t)0 * Bn + b) * NSL + sl) * Cn + h * 64 + dd];
        ksum += nss[(((size_t)1 * Bn + b) * NSL + sl) * Cn + h * 64 + e];
    }
    const float rq = 1.0f / fmaxf(sqrtf(qsum), 1e-12f);
    const float rk = 1.0f / fmaxf(sqrtf(ksum), 1e-12f);

    float s = 0.f;
    #pragma unroll
    for (int sp = 0; sp < GSP; sp++)
        s += Gp[(((size_t)bh * GSP + sp) << 12) + dd * 64 + e];
    s *= rq * rk * temp[h];

    __shared__ float red[64];
    red[e] = s;
    __syncthreads();
    for (int st = 32; st > 0; st >>= 1) {
        if (e < st) red[e] = fmaxf(red[e], red[e + st]);
        __syncthreads();
    }
    float m = red[0];
    __syncthreads();
    float ex = __expf(s - m);
    red[e] = ex;
    __syncthreads();
    for (int st = 32; st > 0; st >>= 1) {
        if (e < st) red[e] += red[e + st];
        __syncthreads();
    }
    A[(size_t)bh * 4096 + dd * 64 + e] = ex / red[0];
}

// ---------------------------------------------------------------------------
// fold1: U_b[h*64+dd][k] = sum_e attn[bh][dd][e] * Wv[h*64+e][k]   (fp32)
// ---------------------------------------------------------------------------
__global__ void __launch_bounds__(256) fold1_kernel(const float* __restrict__ A,
                                                    const float* __restrict__ Wv,
                                                    float* __restrict__ U)
{
    __shared__ float at[64][65];
    __shared__ float wv[64][65];
    const int bh = blockIdx.x, kq = blockIdx.y;
    const int b = bh >> 2, h = bh & 3;
    const int tx = threadIdx.x & 15, ty = threadIdx.x >> 4;
    const int tid = threadIdx.x;

    const float* Ab = A + (size_t)bh * 4096;
    #pragma unroll
    for (int i = 0; i < 16; i++) {
        int idx = tid + i * 256;
        at[idx >> 6][idx & 63] = Ab[idx];
    }
    #pragma unroll
    for (int i = 0; i < 16; i++) {
        int idx = tid + i * 256;
        wv[idx >> 6][idx & 63] = Wv[(size_t)(h * 64 + (idx >> 6)) * 256 + kq * 64 + (idx & 63)];
    }
    __syncthreads();

    float acc[4][4] = {};
    #pragma unroll
    for (int e = 0; e < 64; e++) {
        float av[4], bv[4];
        #pragma unroll
        for (int i = 0; i < 4; i++) av[i] = at[ty * 4 + i][e];
        #pragma unroll
        for (int j = 0; j < 4; j++) bv[j] = wv[e][tx * 4 + j];
        #pragma unroll
        for (int i = 0; i < 4; i++)
            #pragma unroll
            for (int j = 0; j < 4; j++)
                acc[i][j] += av[i] * bv[j];
    }
    #pragma unroll
    for (int i = 0; i < 4; i++)
        #pragma unroll
        for (int j = 0; j < 4; j++)
            U[((size_t)b * 256 + h * 64 + ty * 4 + i) * 256 + kq * 64 + tx * 4 + j] = acc[i][j];
}

// ---------------------------------------------------------------------------
// fold2: W2_b[c][k] = sum_ddg Wo[c][ddg] * U_b[ddg][k]   -> fp16
// ---------------------------------------------------------------------------
__global__ void __launch_bounds__(256) fold2_kernel(const float* __restrict__ Wo,
                                                    const float* __restrict__ U,
                                                    __half* __restrict__ W2)
{
    __shared__ float ws[16][68];
    __shared__ float us[16][68];
    const int cq = blockIdx.x, kq = blockIdx.y, b = blockIdx.z;
    const int tid = threadIdx.x;
    const int tx = tid & 15, ty = tid >> 4;
    const int lrow = tid >> 2, lk4 = (tid & 3) * 4;
    const int krow = tid >> 4, kc4 = (tid & 15) * 4;

    const float* Ub = U + ((size_t)b << 16);
    float acc[4][4] = {};

    for (int k0 = 0; k0 < 256; k0 += 16) {
        float4 wv4 = *reinterpret_cast<const float4*>(
            Wo + (size_t)(cq * 64 + lrow) * 256 + k0 + lk4);
        float4 uv4 = *reinterpret_cast<const float4*>(
            Ub + (size_t)(k0 + krow) * 256 + kq * 64 + kc4);
        __syncthreads();
        ws[lk4+0][lrow] = wv4.x; ws[lk4+1][lrow] = wv4.y;
        ws[lk4+2][lrow] = wv4.z; ws[lk4+3][lrow] = wv4.w;
        *reinterpret_cast<float4*>(&us[krow][kc4]) = uv4;
        __syncthreads();
        #pragma unroll
        for (int kk = 0; kk < 16; kk++) {
            float4 a = *reinterpret_cast<const float4*>(&ws[kk][ty * 4]);
            float4 bb = *reinterpret_cast<const float4*>(&us[kk][tx * 4]);
            float av[4] = {a.x, a.y, a.z, a.w};
            float bv[4] = {bb.x, bb.y, bb.z, bb.w};
            #pragma unroll
            for (int i = 0; i < 4; i++)
                #pragma unroll
                for (int j = 0; j < 4; j++)
                    acc[i][j] += av[i] * bv[j];
        }
    }
    #pragma unroll
    for (int i = 0; i < 4; i++)
        #pragma unroll
        for (int j = 0; j < 4; j++)
            W2[((size_t)b << 16) + (size_t)(cq * 64 + ty * 4 + i) * 256 + kq * 64 + tx * 4 + j] =
                __float2half(acc[i][j]);
}

// ---------------------------------------------------------------------------
extern "C" void kernel_launch(void* const* d_in, const int* in_sizes, int n_in,
                              void* d_out, int out_size)
{
    (void)in_sizes; (void)n_in; (void)out_size;
    const float* x1 = (const float*)d_in[0];
    const float* x2 = (const float*)d_in[1];
    const float* Wq = (const float*)d_in[2];
    const float* Wk = (const float*)d_in[3];
    const float* Wv = (const float*)d_in[4];
    const float* Wo = (const float*)d_in[5];
    const float* bo = (const float*)d_in[6];
    const float* temperature = (const float*)d_in[7];
    float* out = (float*)d_out;

    __half *x1h, *x2h, *qh, *kh, *wh, *w2h;
    float *u, *gp, *attn, *nss;
    cudaGetSymbolAddress((void**)&x1h, g_x1h);
    cudaGetSymbolAddress((void**)&x2h, g_x2h);
    cudaGetSymbolAddress((void**)&qh,  g_qh);
    cudaGetSymbolAddress((void**)&kh,  g_kh);
    cudaGetSymbolAddress((void**)&wh,  g_wh);
    cudaGetSymbolAddress((void**)&w2h, g_w2h);
    cudaGetSymbolAddress((void**)&u,   g_u);
    cudaGetSymbolAddress((void**)&gp,  g_gp);
    cudaGetSymbolAddress((void**)&attn, g_attn);
    cudaGetSymbolAddress((void**)&nss, g_nss);

    cudaFuncSetAttribute(gemm_h<false>, cudaFuncAttributeMaxDynamicSharedMemorySize, SMEM_G);
    cudaFuncSetAttribute(gemm_h<true >, cudaFuncAttributeMaxDynamicSharedMemorySize, SMEM_G);

    cvt_w_kernel<<<dim3(64, 2), 256>>>((const float4*)Wq, (const float4*)Wk, wh);
    cvt_x_kernel<<<dim3(1024, 2), 256>>>((const float4*)x1, (const float4*)x2, x1h, x2h);

    // q = x1 @ Wq^T,  k = x2 @ Wk^T   (merged, z selects)
    gemm_h<false><<<dim3(MTOT / 128, 1, 2), 512, SMEM_G>>>(
        x1h, wh, qh, x2h, wh + Cn * Cn, kh, nullptr, nullptr);

    sumsq_kernel<<<dim3(NSL, Bn, 2), 256>>>(qh, kh, nss);
    gram_mma<<<dim3(BHn, GSP), 256>>>(qh, kh, gp);
    softmax_kernel<<<BHn * Dn, 64>>>(gp, nss, temperature, attn);

    fold1_kernel<<<dim3(BHn, 4), 256>>>(attn, Wv, u);
    fold2_kernel<<<dim3(4, 4, Bn), 256>>>(Wo, u, w2h);

    // out = x2 @ W2_b^T + bo
    gemm_h<true><<<dim3(MTOT / 128, 1, 1), 512, SMEM_G>>>(
        x2h, w2h, nullptr, nullptr, nullptr, nullptr, bo, out);
}

// round 8
// speedup vs baseline: 6.4034x; 1.2203x over previous
#include <cuda_runtime.h>
#include <cuda_fp16.h>
#include <math.h>
#include <stdint.h>

#define Bn 8
#define Nn 8192
#define Cn 256
#define Hn 4
#define Dn 64
#define BHn (Bn*Hn)
#define MTOT (Bn*Nn)
#define GSP 8
#define GSL (Nn/GSP)
#define NCTA (MTOT/128)   // 512

// ---------------------------------------------------------------------------
// Scratch (__device__ globals; no allocation allowed)
// ---------------------------------------------------------------------------
__device__ __half g_qh [MTOT*Cn];
__device__ __half g_kh [MTOT*Cn];
__device__ __half g_wh [2*Cn*Cn];
__device__ __half g_w2h[Bn*Cn*Cn];
__device__ float  g_u  [Bn*Cn*Cn];
__device__ float  g_gp [BHn*GSP*Dn*Dn];
__device__ float  g_attn[BHn*Dn*Dn];
__device__ float  g_nssp[2*NCTA*Cn];   // per-CTA column sumsq partials
__device__ float  g_nss2[2*Bn*Cn];     // reduced norms

// ---------------------------------------------------------------------------
// Helpers
// ---------------------------------------------------------------------------
__device__ __forceinline__ uint32_t smem_u32(const void* p) {
    uint32_t a;
    asm("{ .reg .u64 t; cvta.to.shared.u64 t, %1; cvt.u32.u64 %0, t; }" : "=r"(a) : "l"(p));
    return a;
}
__device__ __forceinline__ void cp16(uint32_t sdst, const void* gsrc) {
    asm volatile("cp.async.cg.shared.global [%0], [%1], 16;"
                 :: "r"(sdst), "l"(__cvta_generic_to_global(gsrc)) : "memory");
}
#define CP_COMMIT() asm volatile("cp.async.commit_group;" ::: "memory")
#define CP_WAIT2()  asm volatile("cp.async.wait_group 2;" ::: "memory")
#define CP_WAIT1()  asm volatile("cp.async.wait_group 1;" ::: "memory")

#define LDSM4(r0, r1, r2, r3, addr) \
    asm volatile("ldmatrix.sync.aligned.m8n8.x4.shared.b16 {%0,%1,%2,%3}, [%4];" \
                 : "=r"(r0), "=r"(r1), "=r"(r2), "=r"(r3) : "r"(addr))
#define LDSM4T(r0, r1, r2, r3, addr) \
    asm volatile("ldmatrix.sync.aligned.m8n8.x4.trans.shared.b16 {%0,%1,%2,%3}, [%4];" \
                 : "=r"(r0), "=r"(r1), "=r"(r2), "=r"(r3) : "r"(addr))
#define LDSM2T(r0, r1, addr) \
    asm volatile("ldmatrix.sync.aligned.m8n8.x2.trans.shared.b16 {%0,%1}, [%2];" \
                 : "=r"(r0), "=r"(r1) : "r"(addr))

__device__ __forceinline__ void mma_f16(float* d, const uint32_t* a, const uint32_t* b) {
    asm volatile(
        "mma.sync.aligned.m16n8k16.row.col.f32.f16.f16.f32 "
        "{%0,%1,%2,%3}, {%4,%5,%6,%7}, {%8,%9}, {%0,%1,%2,%3};"
        : "+f"(d[0]), "+f"(d[1]), "+f"(d[2]), "+f"(d[3])
        : "r"(a[0]), "r"(a[1]), "r"(a[2]), "r"(a[3]), "r"(b[0]), "r"(b[1]));
}

// ---------------------------------------------------------------------------
// fp16 mma GEMM with fp32 A operand (converted in-flight), CTA 128x256,
// 512 threads (warps 4Mx4N, 32x64 each), K=256 in 8 chunks of 32.
// A: LDG float4 -> cvt -> STS fp16 (register prefetch, depth 3).
// B: cp.async fp16 (weights).
// !OUTF32: fp16 output + fused column-sumsq partials (for q/k norms).
//  OUTF32: fp32 output + bias, per-batch folded weight.
// ---------------------------------------------------------------------------
#define RSH 40
#define A_STG (128*RSH*2)               // 10240 B
#define B_STG (256*RSH*2)               // 20480 B
#define SMEM_T (4*(A_STG+B_STG) + 4096) // 126976 B

template<bool OUTF32>
__global__ void __launch_bounds__(512, 1) gemm_h(const float* __restrict__ X0,
                                                 const __half* __restrict__ W0,
                                                 __half* __restrict__ Yh0,
                                                 const float* __restrict__ X1,
                                                 const __half* __restrict__ W1,
                                                 __half* __restrict__ Yh1,
                                                 const float* __restrict__ bias,
                                                 float* __restrict__ Yf,
                                                 float* __restrict__ nssp)
{
    extern __shared__ char sm[];
    const uint32_t sA = smem_u32(sm);
    const uint32_t sB = sA + 4 * A_STG;
    float* part = reinterpret_cast<float*>(sm + 4 * (A_STG + B_STG));

    const int tid  = threadIdx.x;
    const int wid  = tid >> 5, lane = tid & 31;
    const int wm   = wid & 3;
    const int wn   = wid >> 2;
    const int gid  = lane >> 2;
    const int tig  = lane & 3;
    const int m0   = blockIdx.x * 128;
    const int z    = OUTF32 ? 0 : blockIdx.z;

    const float* X = (!OUTF32 && z) ? X1 : X0;
    const __half* Wp = OUTF32 ? W0 + ((size_t)(m0 >> 13) << 16) : (z ? W1 : W0);
    __half* Yh = z ? Yh1 : Yh0;

    const int lrA = ((lane >> 3) & 1) * 8 + (lane & 7);
    const int lkA = (lane >> 4) * 8;
    const int lrB = (lane >> 4) * 8 + (lane & 7);
    const int lkB = ((lane >> 3) & 1) * 8;
    int aoffs[2], boffs[4];
    #pragma unroll
    for (int mt = 0; mt < 2; mt++) aoffs[mt] = (wm * 32 + mt * 16 + lrA) * RSH + lkA;
    #pragma unroll
    for (int nb = 0; nb < 4; nb++) boffs[nb] = (wn * 64 + nb * 16 + lrB) * RSH + lkB;

    // A: 128 rows x 32 fp32 per chunk = 1024 float4; 2 per thread
    const int ag0 = tid, ag1 = tid + 512;
    auto ldA = [&](int k0, float4& p0, float4& p1) {
        p0 = *reinterpret_cast<const float4*>(
            X + (size_t)(m0 + (ag0 >> 3)) * Cn + k0 + (ag0 & 7) * 4);
        p1 = *reinterpret_cast<const float4*>(
            X + (size_t)(m0 + (ag1 >> 3)) * Cn + k0 + (ag1 & 7) * 4);
    };
    auto stA1 = [&](int st, int g, float4 v) {
        __half2 h0 = __floats2half2_rn(v.x, v.y);
        __half2 h1 = __floats2half2_rn(v.z, v.w);
        uint2 u;
        u.x = *reinterpret_cast<uint32_t*>(&h0);
        u.y = *reinterpret_cast<uint32_t*>(&h1);
        *reinterpret_cast<uint2*>(sm + st * A_STG + ((g >> 3) * RSH + (g & 7) * 4) * 2) = u;
    };

    auto loadB = [&](int st, int k0) {
        #pragma unroll
        for (int i = 0; i < 2; i++) {
            int g = tid + i * 512;
            int r = g >> 2, kq = g & 3;
            cp16(sB + st * B_STG + (r * RSH + kq * 8) * 2,
                 Wp + (size_t)r * Cn + k0 + kq * 8);
        }
    };

    float acc[2][8][4] = {};
    float4 pa, pb;

    // prologue: stages 0..2
    {
        float4 q0, q1, r0, r1, s0, s1;
        ldA(0, q0, q1); ldA(32, r0, r1); ldA(64, s0, s1);
        stA1(0, ag0, q0); stA1(0, ag1, q1);
        stA1(1, ag0, r0); stA1(1, ag1, r1);
        stA1(2, ag0, s0); stA1(2, ag1, s1);
        loadB(0, 0);  CP_COMMIT();
        loadB(1, 32); CP_COMMIT();
        loadB(2, 64); CP_COMMIT();
    }

    for (int ch = 0; ch < 8; ch++) {
        if (ch + 3 < 8) ldA((ch + 3) * 32, pa, pb);
        CP_WAIT2();
        __syncthreads();

        const int st = ch & 3;
        const uint32_t a0 = sA + st * A_STG;
        const uint32_t b0a = sB + st * B_STG;

        #pragma unroll
        for (int ks = 0; ks < 2; ks++) {
            uint32_t af[2][4];
            #pragma unroll
            for (int mt = 0; mt < 2; mt++)
                LDSM4(af[mt][0], af[mt][1], af[mt][2], af[mt][3],
                      a0 + (aoffs[mt] + ks * 16) * 2);
            uint32_t bf[8][2];
            #pragma unroll
            for (int nb = 0; nb < 4; nb++) {
                uint32_t r0, r1, r2, r3;
                LDSM4(r0, r1, r2, r3, b0a + (boffs[nb] + ks * 16) * 2);
                bf[nb * 2][0] = r0; bf[nb * 2][1] = r1;
                bf[nb * 2 + 1][0] = r2; bf[nb * 2 + 1][1] = r3;
            }
            #pragma unroll
            for (int mt = 0; mt < 2; mt++)
                #pragma unroll
                for (int nt = 0; nt < 8; nt++)
                    mma_f16(acc[mt][nt], af[mt], bf[nt]);
        }

        if (ch + 3 < 8) {
            const int sn = (ch + 3) & 3;
            stA1(sn, ag0, pa); stA1(sn, ag1, pb);
            loadB(sn, (ch + 3) * 32);
        }
        CP_COMMIT();
    }

    // Output
    #pragma unroll
    for (int mt = 0; mt < 2; mt++) {
        const int m = m0 + wm * 32 + mt * 16 + gid;
        #pragma unroll
        for (int nt = 0; nt < 8; nt++) {
            const int cg = wn * 64 + nt * 8 + tig * 2;
            if (OUTF32) {
                float b0 = __ldg(bias + cg), b1 = __ldg(bias + cg + 1);
                float2 v0 = make_float2(acc[mt][nt][0] + b0, acc[mt][nt][1] + b1);
                float2 v1 = make_float2(acc[mt][nt][2] + b0, acc[mt][nt][3] + b1);
                *reinterpret_cast<float2*>(Yf + (size_t)m * Cn + cg)       = v0;
                *reinterpret_cast<float2*>(Yf + (size_t)(m + 8) * Cn + cg) = v1;
            } else {
                __half2 h0 = __floats2half2_rn(acc[mt][nt][0], acc[mt][nt][1]);
                __half2 h1 = __floats2half2_rn(acc[mt][nt][2], acc[mt][nt][3]);
                *reinterpret_cast<__half2*>(Yh + (size_t)m * Cn + cg)       = h0;
                *reinterpret_cast<__half2*>(Yh + (size_t)(m + 8) * Cn + cg) = h1;
            }
        }
    }

    if (!OUTF32) {
        // Fused column sum-of-squares over this CTA's 128 rows
        float cs[8][2];
        #pragma unroll
        for (int nt = 0; nt < 8; nt++) {
            cs[nt][0] = acc[0][nt][0] * acc[0][nt][0] + acc[0][nt][2] * acc[0][nt][2]
                      + acc[1][nt][0] * acc[1][nt][0] + acc[1][nt][2] * acc[1][nt][2];
            cs[nt][1] = acc[0][nt][1] * acc[0][nt][1] + acc[0][nt][3] * acc[0][nt][3]
                      + acc[1][nt][1] * acc[1][nt][1] + acc[1][nt][3] * acc[1][nt][3];
        }
        #pragma unroll
        for (int nt = 0; nt < 8; nt++)
            #pragma unroll
            for (int j = 0; j < 2; j++) {
                cs[nt][j] += __shfl_xor_sync(0xffffffffu, cs[nt][j], 4);
                cs[nt][j] += __shfl_xor_sync(0xffffffffu, cs[nt][j], 8);
                cs[nt][j] += __shfl_xor_sync(0xffffffffu, cs[nt][j], 16);
            }
        if (gid == 0) {
            #pragma unroll
            for (int nt = 0; nt < 8; nt++) {
                part[wm * 256 + wn * 64 + nt * 8 + tig * 2]     = cs[nt][0];
                part[wm * 256 + wn * 64 + nt * 8 + tig * 2 + 1] = cs[nt][1];
            }
        }
        __syncthreads();
        if (tid < 256) {
            float s = part[tid] + part[256 + tid] + part[512 + tid] + part[768 + tid];
            nssp[((size_t)z * NCTA + blockIdx.x) * 256 + tid] = s;
        }
    }
}

// ---------------------------------------------------------------------------
// Reduce per-CTA sumsq partials -> per-batch norms (deterministic order)
// ---------------------------------------------------------------------------
__global__ void __launch_bounds__(256) reduce_nss(const float* __restrict__ nssp,
                                                  float* __restrict__ nss2)
{
    const int b = blockIdx.x, z = blockIdx.y, c = threadIdx.x;
    float s = 0.f;
    #pragma unroll 8
    for (int i = 0; i < 64; i++)
        s += nssp[((size_t)z * NCTA + b * 64 + i) * 256 + c];
    nss2[(z * Bn + b) * 256 + c] = s;
}

// ---------------------------------------------------------------------------
// Gram via fp16 mma with ldmatrix.trans
// ---------------------------------------------------------------------------
#define GRS 72
#define GSTG (64*GRS*2)

__global__ void __launch_bounds__(256, 2) gram_mma(const __half* __restrict__ Qh,
                                                   const __half* __restrict__ Kh,
                                                   float* __restrict__ Gp)
{
    __shared__ char smg[4 * GSTG];
    const uint32_t sq = smem_u32(smg);
    const uint32_t sk = sq + 2 * GSTG;

    const int bh = blockIdx.x, sp = blockIdx.y;
    const int b = bh >> 2, h = bh & 3;
    const int tid = threadIdx.x;
    const int w = tid >> 5, lane = tid & 31;
    const int gid = lane >> 2, tig = lane & 3;
    const int t0 = sp * GSL;

    const __half* qb = Qh + ((size_t)b * Nn) * 256 + h * 64;
    const __half* kb = Kh + ((size_t)b * Nn) * 256 + h * 64;

    auto gload = [&](int st, int tc) {
        #pragma unroll
        for (int i = 0; i < 2; i++) {
            int g = tid + i * 256;
            int r = g >> 3, ck = g & 7;
            cp16(sq + st * GSTG + (r * GRS + ck * 8) * 2,
                 qb + (size_t)(t0 + tc + r) * 256 + ck * 8);
        }
        #pragma unroll
        for (int i = 0; i < 2; i++) {
            int g = tid + i * 256;
            int r = g >> 3, ck = g & 7;
            cp16(sk + st * GSTG + (r * GRS + ck * 8) * 2,
                 kb + (size_t)(t0 + tc + r) * 256 + ck * 8);
        }
    };

    const int aH = (((lane >> 4) & 1) * 8 + (lane & 7)) * GRS + ((lane >> 3) & 1) * 8;
    const int bH = (((lane >> 3) & 1) * 8 + (lane & 7)) * GRS + w * 8;

    float acc[4][4] = {};

    gload(0, 0);  CP_COMMIT();
    gload(1, 64); CP_COMMIT();

    for (int c = 0; c < 16; c++) {
        CP_WAIT1();
        __syncthreads();
        const uint32_t aq = sq + (c & 1) * GSTG;
        const uint32_t ak = sk + (c & 1) * GSTG;

        #pragma unroll
        for (int st16 = 0; st16 < 4; st16++) {
            const int kb16 = st16 * 16;
            uint32_t bfr[2];
            LDSM2T(bfr[0], bfr[1], ak + (kb16 * GRS + bH) * 2);
            #pragma unroll
            for (int mt = 0; mt < 4; mt++) {
                uint32_t af[4];
                LDSM4T(af[0], af[1], af[2], af[3],
                       aq + (kb16 * GRS + aH + mt * 16) * 2);
                mma_f16(acc[mt], af, bfr);
            }
        }
        __syncthreads();
        if (c + 2 < 16) gload(c & 1, (c + 2) * 64);
        CP_COMMIT();
    }

    float* g = Gp + (((size_t)bh * GSP + sp) << 12);
    #pragma unroll
    for (int mt = 0; mt < 4; mt++) {
        const int r0 = mt * 16 + gid;
        *reinterpret_cast<float2*>(g + r0 * 64 + w * 8 + tig * 2) =
            make_float2(acc[mt][0], acc[mt][1]);
        *reinterpret_cast<float2*>(g + (r0 + 8) * 64 + w * 8 + tig * 2) =
            make_float2(acc[mt][2], acc[mt][3]);
    }
}

// ---------------------------------------------------------------------------
// Weight f32 -> f16
// ---------------------------------------------------------------------------
__device__ __forceinline__ void cvt_store4(__half* dst, float4 v) {
    __half2 h0 = __floats2half2_rn(v.x, v.y);
    __half2 h1 = __floats2half2_rn(v.z, v.w);
    uint2 u;
    u.x = *reinterpret_cast<uint32_t*>(&h0);
    u.y = *reinterpret_cast<uint32_t*>(&h1);
    *reinterpret_cast<uint2*>(dst) = u;
}

__global__ void __launch_bounds__(256) cvt_w_kernel(const float4* __restrict__ wq,
                                                    const float4* __restrict__ wk,
                                                    __half* dst)
{
    const int n4 = (Cn * Cn) / 4;
    const float4* src = blockIdx.y == 0 ? wq : wk;
    __half* d = dst + (size_t)blockIdx.y * Cn * Cn;
    int i = blockIdx.x * 256 + threadIdx.x;
    if (i < n4) cvt_store4(d + i * 4, src[i]);
}

// ---------------------------------------------------------------------------
// Reduce gram partials, normalize * temperature, softmax
// ---------------------------------------------------------------------------
__global__ void __launch_bounds__(64) softmax_kernel(const float* __restrict__ Gp,
                                                     const float* __restrict__ nss2,
                                                     const float* __restrict__ temp,
                                                     float* __restrict__ A)
{
    const int r  = blockIdx.x;
    const int bh = r >> 6;
    const int dd = r & 63;
    const int b  = bh >> 2, h = bh & 3;
    const int e  = threadIdx.x;

    const float rq = 1.0f / fmaxf(sqrtf(nss2[(0 * Bn + b) * 256 + h * 64 + dd]), 1e-12f);
    const float rk = 1.0f / fmaxf(sqrtf(nss2[(1 * Bn + b) * 256 + h * 64 + e]), 1e-12f);

    float s = 0.f;
    #pragma unroll
    for (int sp = 0; sp < GSP; sp++)
        s += Gp[(((size_t)bh * GSP + sp) << 12) + dd * 64 + e];
    s *= rq * rk * temp[h];

    __shared__ float red[64];
    red[e] = s;
    __syncthreads();
    for (int st = 32; st > 0; st >>= 1) {
        if (e < st) red[e] = fmaxf(red[e], red[e + st]);
        __syncthreads();
    }
    float m = red[0];
    __syncthreads();
    float ex = __expf(s - m);
    red[e] = ex;
    __syncthreads();
    for (int st = 32; st > 0; st >>= 1) {
        if (e < st) red[e] += red[e + st];
        __syncthreads();
    }
    A[(size_t)bh * 4096 + dd * 64 + e] = ex / red[0];
}

// ---------------------------------------------------------------------------
// fold1: U_b[h*64+dd][k] = sum_e attn[bh][dd][e] * Wv[h*64+e][k]   (fp32)
// ---------------------------------------------------------------------------
__global__ void __launch_bounds__(256) fold1_kernel(const float* __restrict__ A,
                                                    const float* __restrict__ Wv,
                                                    float* __restrict__ U)
{
    __shared__ float at[64][65];
    __shared__ float wv[64][65];
    const int bh = blockIdx.x, kq = blockIdx.y;
    const int b = bh >> 2, h = bh & 3;
    const int tx = threadIdx.x & 15, ty = threadIdx.x >> 4;
    const int tid = threadIdx.x;

    const float* Ab = A + (size_t)bh * 4096;
    #pragma unroll
    for (int i = 0; i < 16; i++) {
        int idx = tid + i * 256;
        at[idx >> 6][idx & 63] = Ab[idx];
    }
    #pragma unroll
    for (int i = 0; i < 16; i++) {
        int idx = tid + i * 256;
        wv[idx >> 6][idx & 63] = Wv[(size_t)(h * 64 + (idx >> 6)) * 256 + kq * 64 + (idx & 63)];
    }
    __syncthreads();

    float acc[4][4] = {};
    #pragma unroll
    for (int e = 0; e < 64; e++) {
        float av[4], bv[4];
        #pragma unroll
        for (int i = 0; i < 4; i++) av[i] = at[ty * 4 + i][e];
        #pragma unroll
        for (int j = 0; j < 4; j++) bv[j] = wv[e][tx * 4 + j];
        #pragma unroll
        for (int i = 0; i < 4; i++)
            #pragma unroll
            for (int j = 0; j < 4; j++)
                acc[i][j] += av[i] * bv[j];
    }
    #pragma unroll
    for (int i = 0; i < 4; i++)
        #pragma unroll
        for (int j = 0; j < 4; j++)
            U[((size_t)b * 256 + h * 64 + ty * 4 + i) * 256 + kq * 64 + tx * 4 + j] = acc[i][j];
}

// ---------------------------------------------------------------------------
// fold2: W2_b[c][k] = sum_ddg Wo[c][ddg] * U_b[ddg][k]   -> fp16
// ---------------------------------------------------------------------------
__global__ void __launch_bounds__(256) fold2_kernel(const float* __restrict__ Wo,
                                                    const float* __restrict__ U,
                                                    __half* __restrict__ W2)
{
    __shared__ float ws[16][68];
    __shared__ float us[16][68];
    const int cq = blockIdx.x, kq = blockIdx.y, b = blockIdx.z;
    const int tid = threadIdx.x;
    const int tx = tid & 15, ty = tid >> 4;
    const int lrow = tid >> 2, lk4 = (tid & 3) * 4;
    const int krow = tid >> 4, kc4 = (tid & 15) * 4;

    const float* Ub = U + ((size_t)b << 16);
    float acc[4][4] = {};

    for (int k0 = 0; k0 < 256; k0 += 16) {
        float4 wv4 = *reinterpret_cast<const float4*>(
            Wo + (size_t)(cq * 64 + lrow) * 256 + k0 + lk4);
        float4 uv4 = *reinterpret_cast<const float4*>(
            Ub + (size_t)(k0 + krow) * 256 + kq * 64 + kc4);
        __syncthreads();
        ws[lk4+0][lrow] = wv4.x; ws[lk4+1][lrow] = wv4.y;
        ws[lk4+2][lrow] = wv4.z; ws[lk4+3][lrow] = wv4.w;
        *reinterpret_cast<float4*>(&us[krow][kc4]) = uv4;
        __syncthreads();
        #pragma unroll
        for (int kk = 0; kk < 16; kk++) {
            float4 a = *reinterpret_cast<const float4*>(&ws[kk][ty * 4]);
            float4 bb = *reinterpret_cast<const float4*>(&us[kk][tx * 4]);
            float av[4] = {a.x, a.y, a.z, a.w};
            float bv[4] = {bb.x, bb.y, bb.z, bb.w};
            #pragma unroll
            for (int i = 0; i < 4; i++)
                #pragma unroll
                for (int j = 0; j < 4; j++)
                    acc[i][j] += av[i] * bv[j];
        }
    }
    #pragma unroll
    for (int i = 0; i < 4; i++)
        #pragma unroll
        for (int j = 0; j < 4; j++)
            W2[((size_t)b << 16) + (size_t)(cq * 64 + ty * 4 + i) * 256 + kq * 64 + tx * 4 + j] =
                __float2half(acc[i][j]);
}

// ---------------------------------------------------------------------------
extern "C" void kernel_launch(void* const* d_in, const int* in_sizes, int n_in,
                              void* d_out, int out_size)
{
    (void)in_sizes; (void)n_in; (void)out_size;
    const float* x1 = (const float*)d_in[0];
    const float* x2 = (const float*)d_in[1];
    const float* Wq = (const float*)d_in[2];
    const float* Wk = (const float*)d_in[3];
    const float* Wv = (const float*)d_in[4];
    const float* Wo = (const float*)d_in[5];
    const float* bo = (const float*)d_in[6];
    const float* temperature = (const float*)d_in[7];
    float* out = (float*)d_out;

    __half *qh, *kh, *wh, *w2h;
    float *u, *gp, *attn, *nssp, *nss2;
    cudaGetSymbolAddress((void**)&qh,  g_qh);
    cudaGetSymbolAddress((void**)&kh,  g_kh);
    cudaGetSymbolAddress((void**)&wh,  g_wh);
    cudaGetSymbolAddress((void**)&w2h, g_w2h);
    cudaGetSymbolAddress((void**)&u,   g_u);
    cudaGetSymbolAddress((void**)&gp,  g_gp);
    cudaGetSymbolAddress((void**)&attn, g_attn);
    cudaGetSymbolAddress((void**)&nssp, g_nssp);
    cudaGetSymbolAddress((void**)&nss2, g_nss2);

    cudaFuncSetAttribute(gemm_h<false>, cudaFuncAttributeMaxDynamicSharedMemorySize, SMEM_T);
    cudaFuncSetAttribute(gemm_h<true >, cudaFuncAttributeMaxDynamicSharedMemorySize, SMEM_T);

    cvt_w_kernel<<<dim3(64, 2), 256>>>((const float4*)Wq, (const float4*)Wk, wh);

    // q = x1 @ Wq^T, k = x2 @ Wk^T (z selects), fp32 A read + fused sumsq
    gemm_h<false><<<dim3(NCTA, 1, 2), 512, SMEM_T>>>(
        x1, wh, qh, x2, wh + Cn * Cn, kh, nullptr, nullptr, nssp);

    reduce_nss<<<dim3(Bn, 2), 256>>>(nssp, nss2);
    gram_mma<<<dim3(BHn, GSP), 256>>>(qh, kh, gp);
    softmax_kernel<<<BHn * Dn, 64>>>(gp, nss2, temperature, attn);

    fold1_kernel<<<dim3(BHn, 4), 256>>>(attn, Wv, u);
    fold2_kernel<<<dim3(4, 4, Bn), 256>>>(Wo, u, w2h);

    // out = x2 @ W2_b^T + bo  (fp32 A read)
    gemm_h<true><<<dim3(NCTA, 1, 1), 512, SMEM_T>>>(
        x2, w2h, nullptr, nullptr, nullptr, nullptr, bo, out, nullptr);
}

// round 9
// speedup vs baseline: 6.5116x; 1.0169x over previous
#include <cuda_runtime.h>
#include <cuda_fp16.h>
#include <math.h>
#include <stdint.h>

#define Bn 8
#define Nn 8192
#define Cn 256
#define Hn 4
#define Dn 64
#define BHn (Bn*Hn)
#define MTOT (Bn*Nn)
#define GSP 16
#define GSL (Nn/GSP)
#define NCTA (MTOT/128)   // 512

// ---------------------------------------------------------------------------
// Scratch (__device__ globals; no allocation allowed)
// ---------------------------------------------------------------------------
__device__ __half g_qh [MTOT*Cn];
__device__ __half g_kh [MTOT*Cn];
__device__ __half g_wh [2*Cn*Cn];
__device__ __half g_w2h[Bn*Cn*Cn];
__device__ float  g_u  [Bn*Cn*Cn];
__device__ float  g_gp [BHn*GSP*Dn*Dn];
__device__ float  g_attn[BHn*Dn*Dn];
__device__ float  g_nssp[2*NCTA*Cn];
__device__ float  g_nss2[2*Bn*Cn];

// ---------------------------------------------------------------------------
// Helpers
// ---------------------------------------------------------------------------
__device__ __forceinline__ uint32_t smem_u32(const void* p) {
    uint32_t a;
    asm("{ .reg .u64 t; cvta.to.shared.u64 t, %1; cvt.u32.u64 %0, t; }" : "=r"(a) : "l"(p));
    return a;
}
__device__ __forceinline__ void cp16(uint32_t sdst, const void* gsrc) {
    asm volatile("cp.async.cg.shared.global [%0], [%1], 16;"
                 :: "r"(sdst), "l"(__cvta_generic_to_global(gsrc)) : "memory");
}
#define CP_COMMIT() asm volatile("cp.async.commit_group;" ::: "memory")
#define CP_WAIT1()  asm volatile("cp.async.wait_group 1;" ::: "memory")

#define LDSM4(r0, r1, r2, r3, addr) \
    asm volatile("ldmatrix.sync.aligned.m8n8.x4.shared.b16 {%0,%1,%2,%3}, [%4];" \
                 : "=r"(r0), "=r"(r1), "=r"(r2), "=r"(r3) : "r"(addr))
#define LDSM4T(r0, r1, r2, r3, addr) \
    asm volatile("ldmatrix.sync.aligned.m8n8.x4.trans.shared.b16 {%0,%1,%2,%3}, [%4];" \
                 : "=r"(r0), "=r"(r1), "=r"(r2), "=r"(r3) : "r"(addr))
#define LDSM2T(r0, r1, addr) \
    asm volatile("ldmatrix.sync.aligned.m8n8.x2.trans.shared.b16 {%0,%1}, [%2];" \
                 : "=r"(r0), "=r"(r1) : "r"(addr))

__device__ __forceinline__ void mma_f16(float* d, const uint32_t* a, const uint32_t* b) {
    asm volatile(
        "mma.sync.aligned.m16n8k16.row.col.f32.f16.f16.f32 "
        "{%0,%1,%2,%3}, {%4,%5,%6,%7}, {%8,%9}, {%0,%1,%2,%3};"
        : "+f"(d[0]), "+f"(d[1]), "+f"(d[2]), "+f"(d[3])
        : "r"(a[0]), "r"(a[1]), "r"(a[2]), "r"(a[3]), "r"(b[0]), "r"(b[1]));
}

// ---------------------------------------------------------------------------
// fp16 mma GEMM, fp32 A converted in-flight, CTA 128x256, 512 threads,
// warps 4Mx4N (32x64 each). K=256 in 4 chunks of 64, 3-stage pipeline.
// A: LDG float4 -> cvt -> STS fp16 (register prefetch).  B: cp.async fp16.
// !OUTF32: fp16 out + fused column-sumsq partials.  OUTF32: fp32 out + bias,
// per-batch folded weight.
// ---------------------------------------------------------------------------
#define RSH 72
#define A_STG (128*RSH*2)               // 18432 B
#define B_STG (256*RSH*2)               // 36864 B
#define NST 3
#define SMEM_T (NST*(A_STG+B_STG) + 4096) // 169984 B

template<bool OUTF32>
__global__ void __launch_bounds__(512, 1) gemm_h(const float* __restrict__ X0,
                                                 const __half* __restrict__ W0,
                                                 __half* __restrict__ Yh0,
                                                 const float* __restrict__ X1,
                                                 const __half* __restrict__ W1,
                                                 __half* __restrict__ Yh1,
                                                 const float* __restrict__ bias,
                                                 float* __restrict__ Yf,
                                                 float* __restrict__ nssp)
{
    extern __shared__ char sm[];
    const uint32_t sA = smem_u32(sm);
    const uint32_t sB = sA + NST * A_STG;
    float* part = reinterpret_cast<float*>(sm + NST * (A_STG + B_STG));

    const int tid  = threadIdx.x;
    const int wid  = tid >> 5, lane = tid & 31;
    const int wm   = wid & 3;
    const int wn   = wid >> 2;
    const int gid  = lane >> 2;
    const int tig  = lane & 3;
    const int m0   = blockIdx.x * 128;
    const int z    = OUTF32 ? 0 : blockIdx.z;

    const float* X = (!OUTF32 && z) ? X1 : X0;
    const __half* Wp = OUTF32 ? W0 + ((size_t)(m0 >> 13) << 16) : (z ? W1 : W0);
    __half* Yh = z ? Yh1 : Yh0;

    const int lrA = ((lane >> 3) & 1) * 8 + (lane & 7);
    const int lkA = (lane >> 4) * 8;
    const int lrB = (lane >> 4) * 8 + (lane & 7);
    const int lkB = ((lane >> 3) & 1) * 8;
    int aoffs[2], boffs[4];
    #pragma unroll
    for (int mt = 0; mt < 2; mt++) aoffs[mt] = (wm * 32 + mt * 16 + lrA) * RSH + lkA;
    #pragma unroll
    for (int nb = 0; nb < 4; nb++) boffs[nb] = (wn * 64 + nb * 16 + lrB) * RSH + lkB;

    // A: 128 rows x 64 fp32 per chunk = 2048 float4; 4 per thread
    auto ldA4 = [&](int k0, float4* p) {
        #pragma unroll
        for (int i = 0; i < 4; i++) {
            int g = tid + i * 512;
            p[i] = *reinterpret_cast<const float4*>(
                X + (size_t)(m0 + (g >> 4)) * Cn + k0 + (g & 15) * 4);
        }
    };
    auto stA4 = [&](int st, const float4* p) {
        #pragma unroll
        for (int i = 0; i < 4; i++) {
            int g = tid + i * 512;
            __half2 h0 = __floats2half2_rn(p[i].x, p[i].y);
            __half2 h1 = __floats2half2_rn(p[i].z, p[i].w);
            uint2 u;
            u.x = *reinterpret_cast<uint32_t*>(&h0);
            u.y = *reinterpret_cast<uint32_t*>(&h1);
            *reinterpret_cast<uint2*>(sm + st * A_STG + ((g >> 4) * RSH + (g & 15) * 4) * 2) = u;
        }
    };
    // B: 256 rows x 64 halves per chunk = 2048 cp16; 4 per thread
    auto loadB = [&](int st, int k0) {
        #pragma unroll
        for (int i = 0; i < 4; i++) {
            int g = tid + i * 512;
            int r = g >> 3, kq = g & 7;
            cp16(sB + st * B_STG + (r * RSH + kq * 8) * 2,
                 Wp + (size_t)r * Cn + k0 + kq * 8);
        }
    };

    float acc[2][8][4] = {};

    {   // prologue: stages 0,1
        float4 p0[4], p1[4];
        ldA4(0, p0); ldA4(64, p1);
        stA4(0, p0); loadB(0, 0);  CP_COMMIT();
        stA4(1, p1); loadB(1, 64); CP_COMMIT();
    }

    for (int ch = 0; ch < 4; ch++) {
        float4 pn[4];
        if (ch + 2 < 4) ldA4((ch + 2) * 64, pn);
        CP_WAIT1();
        __syncthreads();

        const int st = ch % 3;
        const uint32_t a0 = sA + st * A_STG;
        const uint32_t b0a = sB + st * B_STG;

        #pragma unroll
        for (int ks = 0; ks < 4; ks++) {
            uint32_t af[2][4];
            #pragma unroll
            for (int mt = 0; mt < 2; mt++)
                LDSM4(af[mt][0], af[mt][1], af[mt][2], af[mt][3],
                      a0 + (aoffs[mt] + ks * 16) * 2);
            uint32_t bf[8][2];
            #pragma unroll
            for (int nb = 0; nb < 4; nb++) {
                uint32_t r0, r1, r2, r3;
                LDSM4(r0, r1, r2, r3, b0a + (boffs[nb] + ks * 16) * 2);
                bf[nb * 2][0] = r0; bf[nb * 2][1] = r1;
                bf[nb * 2 + 1][0] = r2; bf[nb * 2 + 1][1] = r3;
            }
            #pragma unroll
            for (int mt = 0; mt < 2; mt++)
                #pragma unroll
                for (int nt = 0; nt < 8; nt++)
                    mma_f16(acc[mt][nt], af[mt], bf[nt]);
        }

        if (ch + 2 < 4) {
            stA4((ch + 2) % 3, pn);
            loadB((ch + 2) % 3, (ch + 2) * 64);
        }
        CP_COMMIT();
    }

    // Output
    #pragma unroll
    for (int mt = 0; mt < 2; mt++) {
        const int m = m0 + wm * 32 + mt * 16 + gid;
        #pragma unroll
        for (int nt = 0; nt < 8; nt++) {
            const int cg = wn * 64 + nt * 8 + tig * 2;
            if (OUTF32) {
                float b0 = __ldg(bias + cg), b1 = __ldg(bias + cg + 1);
                float2 v0 = make_float2(acc[mt][nt][0] + b0, acc[mt][nt][1] + b1);
                float2 v1 = make_float2(acc[mt][nt][2] + b0, acc[mt][nt][3] + b1);
                *reinterpret_cast<float2*>(Yf + (size_t)m * Cn + cg)       = v0;
                *reinterpret_cast<float2*>(Yf + (size_t)(m + 8) * Cn + cg) = v1;
            } else {
                __half2 h0 = __floats2half2_rn(acc[mt][nt][0], acc[mt][nt][1]);
                __half2 h1 = __floats2half2_rn(acc[mt][nt][2], acc[mt][nt][3]);
                *reinterpret_cast<__half2*>(Yh + (size_t)m * Cn + cg)       = h0;
                *reinterpret_cast<__half2*>(Yh + (size_t)(m + 8) * Cn + cg) = h1;
            }
        }
    }

    if (!OUTF32) {
        float cs[8][2];
        #pragma unroll
        for (int nt = 0; nt < 8; nt++) {
            cs[nt][0] = acc[0][nt][0] * acc[0][nt][0] + acc[0][nt][2] * acc[0][nt][2]
                      + acc[1][nt][0] * acc[1][nt][0] + acc[1][nt][2] * acc[1][nt][2];
            cs[nt][1] = acc[0][nt][1] * acc[0][nt][1] + acc[0][nt][3] * acc[0][nt][3]
                      + acc[1][nt][1] * acc[1][nt][1] + acc[1][nt][3] * acc[1][nt][3];
        }
        #pragma unroll
        for (int nt = 0; nt < 8; nt++)
            #pragma unroll
            for (int j = 0; j < 2; j++) {
                cs[nt][j] += __shfl_xor_sync(0xffffffffu, cs[nt][j], 4);
                cs[nt][j] += __shfl_xor_sync(0xffffffffu, cs[nt][j], 8);
                cs[nt][j] += __shfl_xor_sync(0xffffffffu, cs[nt][j], 16);
            }
        if (gid == 0) {
            #pragma unroll
            for (int nt = 0; nt < 8; nt++) {
                part[wm * 256 + wn * 64 + nt * 8 + tig * 2]     = cs[nt][0];
                part[wm * 256 + wn * 64 + nt * 8 + tig * 2 + 1] = cs[nt][1];
            }
        }
        __syncthreads();
        if (tid < 256) {
            float s = part[tid] + part[256 + tid] + part[512 + tid] + part[768 + tid];
            nssp[((size_t)z * NCTA + blockIdx.x) * 256 + tid] = s;
        }
    }
}

// ---------------------------------------------------------------------------
// Reduce per-CTA sumsq partials -> per-batch norms (deterministic order)
// ---------------------------------------------------------------------------
__global__ void __launch_bounds__(256) reduce_nss(const float* __restrict__ nssp,
                                                  float* __restrict__ nss2)
{
    const int b = blockIdx.x, z = blockIdx.y, c = threadIdx.x;
    float s = 0.f;
    #pragma unroll 8
    for (int i = 0; i < 64; i++)
        s += nssp[((size_t)z * NCTA + b * 64 + i) * 256 + c];
    nss2[(z * Bn + b) * 256 + c] = s;
}

// ---------------------------------------------------------------------------
// Gram via fp16 mma with ldmatrix.trans  (split-K = GSP slices)
// ---------------------------------------------------------------------------
#define GRS 72
#define GSTG (64*GRS*2)

__global__ void __launch_bounds__(256, 2) gram_mma(const __half* __restrict__ Qh,
                                                   const __half* __restrict__ Kh,
                                                   float* __restrict__ Gp)
{
    __shared__ char smg[4 * GSTG];
    const uint32_t sq = smem_u32(smg);
    const uint32_t sk = sq + 2 * GSTG;

    const int bh = blockIdx.x, sp = blockIdx.y;
    const int b = bh >> 2, h = bh & 3;
    const int tid = threadIdx.x;
    const int w = tid >> 5, lane = tid & 31;
    const int gid = lane >> 2, tig = lane & 3;
    const int t0 = sp * GSL;

    const __half* qb = Qh + ((size_t)b * Nn) * 256 + h * 64;
    const __half* kb = Kh + ((size_t)b * Nn) * 256 + h * 64;

    auto gload = [&](int st, int tc) {
        #pragma unroll
        for (int i = 0; i < 2; i++) {
            int g = tid + i * 256;
            int r = g >> 3, ck = g & 7;
            cp16(sq + st * GSTG + (r * GRS + ck * 8) * 2,
                 qb + (size_t)(t0 + tc + r) * 256 + ck * 8);
        }
        #pragma unroll
        for (int i = 0; i < 2; i++) {
            int g = tid + i * 256;
            int r = g >> 3, ck = g & 7;
            cp16(sk + st * GSTG + (r * GRS + ck * 8) * 2,
                 kb + (size_t)(t0 + tc + r) * 256 + ck * 8);
        }
    };

    const int aH = (((lane >> 4) & 1) * 8 + (lane & 7)) * GRS + ((lane >> 3) & 1) * 8;
    const int bH = (((lane >> 3) & 1) * 8 + (lane & 7)) * GRS + w * 8;

    float acc[4][4] = {};

    gload(0, 0);  CP_COMMIT();
    gload(1, 64); CP_COMMIT();

    const int NCH = GSL / 64;
    for (int c = 0; c < NCH; c++) {
        CP_WAIT1();
        __syncthreads();
        const uint32_t aq = sq + (c & 1) * GSTG;
        const uint32_t ak = sk + (c & 1) * GSTG;

        #pragma unroll
        for (int st16 = 0; st16 < 4; st16++) {
            const int kb16 = st16 * 16;
            uint32_t bfr[2];
            LDSM2T(bfr[0], bfr[1], ak + (kb16 * GRS + bH) * 2);
            #pragma unroll
            for (int mt = 0; mt < 4; mt++) {
                uint32_t af[4];
                LDSM4T(af[0], af[1], af[2], af[3],
                       aq + (kb16 * GRS + aH + mt * 16) * 2);
                mma_f16(acc[mt], af, bfr);
            }
        }
        __syncthreads();
        if (c + 2 < NCH) gload(c & 1, (c + 2) * 64);
        CP_COMMIT();
    }

    float* g = Gp + (((size_t)bh * GSP + sp) << 12);
    #pragma unroll
    for (int mt = 0; mt < 4; mt++) {
        const int r0 = mt * 16 + gid;
        *reinterpret_cast<float2*>(g + r0 * 64 + w * 8 + tig * 2) =
            make_float2(acc[mt][0], acc[mt][1]);
        *reinterpret_cast<float2*>(g + (r0 + 8) * 64 + w * 8 + tig * 2) =
            make_float2(acc[mt][2], acc[mt][3]);
    }
}

// ---------------------------------------------------------------------------
// Weight f32 -> f16
// ---------------------------------------------------------------------------
__device__ __forceinline__ void cvt_store4(__half* dst, float4 v) {
    __half2 h0 = __floats2half2_rn(v.x, v.y);
    __half2 h1 = __floats2half2_rn(v.z, v.w);
    uint2 u;
    u.x = *reinterpret_cast<uint32_t*>(&h0);
    u.y = *reinterpret_cast<uint32_t*>(&h1);
    *reinterpret_cast<uint2*>(dst) = u;
}

__global__ void __launch_bounds__(256) cvt_w_kernel(const float4* __restrict__ wq,
                                                    const float4* __restrict__ wk,
                                                    __half* dst)
{
    const int n4 = (Cn * Cn) / 4;
    const float4* src = blockIdx.y == 0 ? wq : wk;
    __half* d = dst + (size_t)blockIdx.y * Cn * Cn;
    int i = blockIdx.x * 256 + threadIdx.x;
    if (i < n4) cvt_store4(d + i * 4, src[i]);
}

// ---------------------------------------------------------------------------
// Reduce gram partials, normalize * temperature, softmax
// ---------------------------------------------------------------------------
__global__ void __launch_bounds__(64) softmax_kernel(const float* __restrict__ Gp,
                                                     const float* __restrict__ nss2,
                                                     const float* __restrict__ temp,
                                                     float* __restrict__ A)
{
    const int r  = blockIdx.x;
    const int bh = r >> 6;
    const int dd = r & 63;
    const int b  = bh >> 2, h = bh & 3;
    const int e  = threadIdx.x;

    const float rq = 1.0f / fmaxf(sqrtf(nss2[(0 * Bn + b) * 256 + h * 64 + dd]), 1e-12f);
    const float rk = 1.0f / fmaxf(sqrtf(nss2[(1 * Bn + b) * 256 + h * 64 + e]), 1e-12f);

    float s = 0.f;
    #pragma unroll
    for (int sp = 0; sp < GSP; sp++)
        s += Gp[(((size_t)bh * GSP + sp) << 12) + dd * 64 + e];
    s *= rq * rk * temp[h];

    __shared__ float red[64];
    red[e] = s;
    __syncthreads();
    for (int st = 32; st > 0; st >>= 1) {
        if (e < st) red[e] = fmaxf(red[e], red[e + st]);
        __syncthreads();
    }
    float m = red[0];
    __syncthreads();
    float ex = __expf(s - m);
    red[e] = ex;
    __syncthreads();
    for (int st = 32; st > 0; st >>= 1) {
        if (e < st) red[e] += red[e + st];
        __syncthreads();
    }
    A[(size_t)bh * 4096 + dd * 64 + e] = ex / red[0];
}

// ---------------------------------------------------------------------------
// fold1: U_b[h*64+dd][k] = sum_e attn[bh][dd][e] * Wv[h*64+e][k]   (fp32)
// ---------------------------------------------------------------------------
__global__ void __launch_bounds__(256) fold1_kernel(const float* __restrict__ A,
                                                    const float* __restrict__ Wv,
                                                    float* __restrict__ U)
{
    __shared__ float at[64][65];
    __shared__ float wv[64][65];
    const int bh = blockIdx.x, kq = blockIdx.y;
    const int b = bh >> 2, h = bh & 3;
    const int tx = threadIdx.x & 15, ty = threadIdx.x >> 4;
    const int tid = threadIdx.x;

    const float* Ab = A + (size_t)bh * 4096;
    #pragma unroll
    for (int i = 0; i < 16; i++) {
        int idx = tid + i * 256;
        at[idx >> 6][idx & 63] = Ab[idx];
    }
    #pragma unroll
    for (int i = 0; i < 16; i++) {
        int idx = tid + i * 256;
        wv[idx >> 6][idx & 63] = Wv[(size_t)(h * 64 + (idx >> 6)) * 256 + kq * 64 + (idx & 63)];
    }
    __syncthreads();

    float acc[4][4] = {};
    #pragma unroll
    for (int e = 0; e < 64; e++) {
        float av[4], bv[4];
        #pragma unroll
        for (int i = 0; i < 4; i++) av[i] = at[ty * 4 + i][e];
        #pragma unroll
        for (int j = 0; j < 4; j++) bv[j] = wv[e][tx * 4 + j];
        #pragma unroll
        for (int i = 0; i < 4; i++)
            #pragma unroll
            for (int j = 0; j < 4; j++)
                acc[i][j] += av[i] * bv[j];
    }
    #pragma unroll
    for (int i = 0; i < 4; i++)
        #pragma unroll
        for (int j = 0; j < 4; j++)
            U[((size_t)b * 256 + h * 64 + ty * 4 + i) * 256 + kq * 64 + tx * 4 + j] = acc[i][j];
}

// ---------------------------------------------------------------------------
// fold2: W2_b[c][k] = sum_ddg Wo[c][ddg] * U_b[ddg][k]   -> fp16
// ---------------------------------------------------------------------------
__global__ void __launch_bounds__(256) fold2_kernel(const float* __restrict__ Wo,
                                                    const float* __restrict__ U,
                                                    __half* __restrict__ W2)
{
    __shared__ float ws[16][68];
    __shared__ float us[16][68];
    const int cq = blockIdx.x, kq = blockIdx.y, b = blockIdx.z;
    const int tid = threadIdx.x;
    const int tx = tid & 15, ty = tid >> 4;
    const int lrow = tid >> 2, lk4 = (tid & 3) * 4;
    const int krow = tid >> 4, kc4 = (tid & 15) * 4;

    const float* Ub = U + ((size_t)b << 16);
    float acc[4][4] = {};

    for (int k0 = 0; k0 < 256; k0 += 16) {
        float4 wv4 = *reinterpret_cast<const float4*>(
            Wo + (size_t)(cq * 64 + lrow) * 256 + k0 + lk4);
        float4 uv4 = *reinterpret_cast<const float4*>(
            Ub + (size_t)(k0 + krow) * 256 + kq * 64 + kc4);
        __syncthreads();
        ws[lk4+0][lrow] = wv4.x; ws[lk4+1][lrow] = wv4.y;
        ws[lk4+2][lrow] = wv4.z; ws[lk4+3][lrow] = wv4.w;
        *reinterpret_cast<float4*>(&us[krow][kc4]) = uv4;
        __syncthreads();
        #pragma unroll
        for (int kk = 0; kk < 16; kk++) {
            float4 a = *reinterpret_cast<const float4*>(&ws[kk][ty * 4]);
            float4 bb = *reinterpret_cast<const float4*>(&us[kk][tx * 4]);
            float av[4] = {a.x, a.y, a.z, a.w};
            float bv[4] = {bb.x, bb.y, bb.z, bb.w};
            #pragma unroll
            for (int i = 0; i < 4; i++)
                #pragma unroll
                for (int j = 0; j < 4; j++)
                    acc[i][j] += av[i] * bv[j];
        }
    }
    #pragma unroll
    for (int i = 0; i < 4; i++)
        #pragma unroll
        for (int j = 0; j < 4; j++)
            W2[((size_t)b << 16) + (size_t)(cq * 64 + ty * 4 + i) * 256 + kq * 64 + tx * 4 + j] =
                __float2half(acc[i][j]);
}

// ---------------------------------------------------------------------------
extern "C" void kernel_launch(void* const* d_in, const int* in_sizes, int n_in,
                              void* d_out, int out_size)
{
    (void)in_sizes; (void)n_in; (void)out_size;
    const float* x1 = (const float*)d_in[0];
    const float* x2 = (const float*)d_in[1];
    const float* Wq = (const float*)d_in[2];
    const float* Wk = (const float*)d_in[3];
    const float* Wv = (const float*)d_in[4];
    const float* Wo = (const float*)d_in[5];
    const float* bo = (const float*)d_in[6];
    const float* temperature = (const float*)d_in[7];
    float* out = (float*)d_out;

    __half *qh, *kh, *wh, *w2h;
    float *u, *gp, *attn, *nssp, *nss2;
    cudaGetSymbolAddress((void**)&qh,  g_qh);
    cudaGetSymbolAddress((void**)&kh,  g_kh);
    cudaGetSymbolAddress((void**)&wh,  g_wh);
    cudaGetSymbolAddress((void**)&w2h, g_w2h);
    cudaGetSymbolAddress((void**)&u,   g_u);
    cudaGetSymbolAddress((void**)&gp,  g_gp);
    cudaGetSymbolAddress((void**)&attn, g_attn);
    cudaGetSymbolAddress((void**)&nssp, g_nssp);
    cudaGetSymbolAddress((void**)&nss2, g_nss2);

    cudaFuncSetAttribute(gemm_h<false>, cudaFuncAttributeMaxDynamicSharedMemorySize, SMEM_T);
    cudaFuncSetAttribute(gemm_h<true >, cudaFuncAttributeMaxDynamicSharedMemorySize, SMEM_T);

    cvt_w_kernel<<<dim3(64, 2), 256>>>((const float4*)Wq, (const float4*)Wk, wh);

    gemm_h<false><<<dim3(NCTA, 1, 2), 512, SMEM_T>>>(
        x1, wh, qh, x2, wh + Cn * Cn, kh, nullptr, nullptr, nssp);

    reduce_nss<<<dim3(Bn, 2), 256>>>(nssp, nss2);
    gram_mma<<<dim3(BHn, GSP), 256>>>(qh, kh, gp);
    softmax_kernel<<<BHn * Dn, 64>>>(gp, nss2, temperature, attn);

    fold1_kernel<<<dim3(BHn, 4), 256>>>(attn, Wv, u);
    fold2_kernel<<<dim3(4, 4, Bn), 256>>>(Wo, u, w2h);

    gemm_h<true><<<dim3(NCTA, 1, 1), 512, SMEM_T>>>(
        x2, w2h, nullptr, nullptr, nullptr, nullptr, bo, out, nullptr);
}